// round 2
// baseline (speedup 1.0000x reference)
#include <cuda_runtime.h>
#include <math.h>

// Problem constants
#define NB 4
#define SQ 1024
#define DM 1024
#define NH 16
#define DKH 64
#define NKV (NB * NH * SQ * DKH)      // 4,194,304 floats per q/k/v
#define NELEM 67108864u               // 4*16*1024*1024 bern elements

// ---------------- scratch (static device globals; no allocs) ----------------
__device__ float g_q[NKV];            // [b,h,s,d]
__device__ float g_k[NKV];
__device__ float g_v[NKV];
__device__ float g_ao[NB * SQ * NH * DKH];        // [b,q,h,d]
__device__ unsigned g_bern[NELEM / 32];           // packed bernoulli bits

// ---------------- threefry2x32, JAX partitionable mode ----------------------
// bits[e] = x0' ^ x1' where (x0,x1) = (hi32(e), lo32(e)) = (0, e), key=(0,42)
__device__ __forceinline__ unsigned rotl32(unsigned x, int r) {
    return __funnelshift_l(x, x, r);
}

__global__ void __launch_bounds__(256) bern_kernel() {
    unsigned e = blockIdx.x * 256u + threadIdx.x;   // element index < NELEM
    unsigned x0 = 0u;          // counts_hi
    unsigned x1 = e;           // counts_lo
    const unsigned ks0 = 0u;
    const unsigned ks1 = 42u;
    const unsigned ks2 = 0x1BD11BDAu ^ 0u ^ 42u;
    x0 += ks0; x1 += ks1;
#define TF_RND(r) { x0 += x1; x1 = rotl32(x1, (r)); x1 ^= x0; }
    TF_RND(13) TF_RND(15) TF_RND(26) TF_RND(6)
    x0 += ks1; x1 += ks2 + 1u;
    TF_RND(17) TF_RND(29) TF_RND(16) TF_RND(24)
    x0 += ks2; x1 += ks0 + 2u;
    TF_RND(13) TF_RND(15) TF_RND(26) TF_RND(6)
    x0 += ks0; x1 += ks1 + 3u;
    TF_RND(17) TF_RND(29) TF_RND(16) TF_RND(24)
    x0 += ks1; x1 += ks2 + 4u;
    TF_RND(13) TF_RND(15) TF_RND(26) TF_RND(6)
    x0 += ks2; x1 += ks0 + 5u;
#undef TF_RND
    unsigned bits = x0 ^ x1;
    // uniform(bits) < 0.3f  <=>  (bits>>9) < 2516583
    unsigned keep = ((bits >> 9) < 2516583u) ? 1u : 0u;
    unsigned w = __ballot_sync(0xffffffffu, keep != 0u);
    if ((threadIdx.x & 31u) == 0u) {
        g_bern[e >> 5] = w;
    }
}

// ---------------- fp32 SGEMM + bias + relu ----------------------------------
// C[M=4096, N=1024] = relu(A[4096,1024] @ W[1024,1024] + bias)
// SCATTER=1: write to [b,h,s,d] layout (q/k/v). SCATTER=0: plain row-major.
template <int SCATTER>
__global__ void __launch_bounds__(256) sgemm_relu_kernel(
    const float* __restrict__ A, const float* __restrict__ W,
    const float* __restrict__ bias, float* __restrict__ out)
{
    const int K = 1024, N = 1024;
    __shared__ float As[16 * 128];  // [k][m]
    __shared__ float Bs[16 * 128];  // [k][n]
    int tid = threadIdx.x;
    int m0 = blockIdx.y * 128;
    int n0 = blockIdx.x * 128;
    int tx = tid & 15, ty = tid >> 4;

    float acc[8][8];
#pragma unroll
    for (int i = 0; i < 8; i++)
#pragma unroll
        for (int jj = 0; jj < 8; jj++) acc[i][jj] = 0.f;

    for (int kt = 0; kt < K; kt += 16) {
#pragma unroll
        for (int i = 0; i < 2; i++) {
            int f4 = tid + i * 256;        // 0..511
            int arow = f4 >> 2, ac4 = f4 & 3;
            float4 av = *(const float4*)(A + (size_t)(m0 + arow) * K + kt + ac4 * 4);
            As[(ac4 * 4 + 0) * 128 + arow] = av.x;
            As[(ac4 * 4 + 1) * 128 + arow] = av.y;
            As[(ac4 * 4 + 2) * 128 + arow] = av.z;
            As[(ac4 * 4 + 3) * 128 + arow] = av.w;
            int brow = f4 >> 5, bc4 = f4 & 31;
            *(float4*)(Bs + brow * 128 + bc4 * 4) =
                *(const float4*)(W + (size_t)(kt + brow) * N + n0 + bc4 * 4);
        }
        __syncthreads();
#pragma unroll
        for (int kk = 0; kk < 16; kk++) {
            float a[8], bb[8];
            *(float4*)(a)      = *(const float4*)(As + kk * 128 + ty * 8);
            *(float4*)(a + 4)  = *(const float4*)(As + kk * 128 + ty * 8 + 4);
            *(float4*)(bb)     = *(const float4*)(Bs + kk * 128 + tx * 8);
            *(float4*)(bb + 4) = *(const float4*)(Bs + kk * 128 + tx * 8 + 4);
#pragma unroll
            for (int i = 0; i < 8; i++)
#pragma unroll
                for (int jj = 0; jj < 8; jj++)
                    acc[i][jj] = fmaf(a[i], bb[jj], acc[i][jj]);
        }
        __syncthreads();
    }

#pragma unroll
    for (int i = 0; i < 8; i++) {
        int row = m0 + ty * 8 + i;
#pragma unroll
        for (int jj = 0; jj < 8; jj++) {
            int col = n0 + tx * 8 + jj;
            float v = fmaxf(acc[i][jj] + bias[col], 0.f);
            if (SCATTER) {
                int b = row >> 10, s = row & 1023;
                int h = col >> 6,  d = col & 63;
                out[(((size_t)(b * NH + h)) * SQ + s) * DKH + d] = v;
            } else {
                out[(size_t)row * N + col] = v;
            }
        }
    }
}

// ---------------- fused attention (flash-style online softmax) --------------
// grid: (q-block 8, h 16, b 4), block: 128 threads; thread t owns q-row qb*128+t
__global__ void __launch_bounds__(128) attn_kernel(
    const float* __restrict__ pos, const int* __restrict__ mask)
{
    int qb = blockIdx.x, h = blockIdx.y, b = blockIdx.z;
    int tid = threadIdx.x;
    int qrow = qb * 128 + tid;

    __shared__ float ks[32][64];
    __shared__ float vs[32][64];
    __shared__ float ps[128][33];   // pos tile, padded

    size_t bh = (size_t)(b * NH + h);
    const float* qp = g_q + (bh * SQ + qrow) * DKH;

    float q[64], o[64];
#pragma unroll
    for (int d = 0; d < 64; d += 4) {
        float4 t = *(const float4*)(qp + d);
        q[d] = t.x; q[d + 1] = t.y; q[d + 2] = t.z; q[d + 3] = t.w;
        o[d] = 0.f; o[d + 1] = 0.f; o[d + 2] = 0.f; o[d + 3] = 0.f;
    }
    float m = -INFINITY, l = 0.f;

    const float4* kbase = (const float4*)(g_k + bh * SQ * DKH);
    const float4* vbase = (const float4*)(g_v + bh * SQ * DKH);
    unsigned bernbase = (unsigned)(bh * SQ + qrow) * 32u;

    for (int kb = 0; kb < SQ; kb += 32) {
        __syncthreads();
        {
            const float4* kg = kbase + kb * 16;   // 16 float4 per key-row
            const float4* vg = vbase + kb * 16;
            float4* ksm = (float4*)&ks[0][0];
            float4* vsm = (float4*)&vs[0][0];
#pragma unroll
            for (int i = 0; i < 4; i++) {
                ksm[tid + i * 128] = kg[tid + i * 128];
                vsm[tid + i * 128] = vg[tid + i * 128];
            }
#pragma unroll
            for (int i = 0; i < 32; i++) {
                int idx = tid + i * 128;          // 0..4095, col fast-varying
                int r = idx >> 5, c = idx & 31;
                ps[r][c] = pos[((size_t)b * SQ + qb * 128 + r) * SQ + kb + c];
            }
        }
        __syncthreads();

        unsigned bw = g_bern[bernbase + (kb >> 5)];

        for (int kk = 0; kk < 32; kk++) {
            int kg = kb + kk;
            float s0 = 0.f, s1 = 0.f, s2 = 0.f, s3 = 0.f;
#pragma unroll
            for (int d = 0; d < 64; d += 16) {
                float4 k0 = *(const float4*)&ks[kk][d];
                float4 k1 = *(const float4*)&ks[kk][d + 4];
                float4 k2 = *(const float4*)&ks[kk][d + 8];
                float4 k3 = *(const float4*)&ks[kk][d + 12];
                s0 = fmaf(q[d], k0.x, s0);      s0 = fmaf(q[d + 1], k0.y, s0);
                s0 = fmaf(q[d + 2], k0.z, s0);  s0 = fmaf(q[d + 3], k0.w, s0);
                s1 = fmaf(q[d + 4], k1.x, s1);  s1 = fmaf(q[d + 5], k1.y, s1);
                s1 = fmaf(q[d + 6], k1.z, s1);  s1 = fmaf(q[d + 7], k1.w, s1);
                s2 = fmaf(q[d + 8], k2.x, s2);  s2 = fmaf(q[d + 9], k2.y, s2);
                s2 = fmaf(q[d + 10], k2.z, s2); s2 = fmaf(q[d + 11], k2.w, s2);
                s3 = fmaf(q[d + 12], k3.x, s3); s3 = fmaf(q[d + 13], k3.y, s3);
                s3 = fmaf(q[d + 14], k3.z, s3); s3 = fmaf(q[d + 15], k3.w, s3);
            }
            float s = (s0 + s1) + (s2 + s3);

            float val = s * 0.125f + ps[tid][kk];
            if ((bw >> kk) & 1u) val = val + (-1e9f);          // fp32 add: exact repro
            if (mask[b * SQ + kg] != 0) val = -1e9f;           // key padding
            if (kg > qrow) val = -1e9f;                        // causal

            if (val > m) {
                float corr = expf(m - val);                    // expf(-inf)=0 first time
                l *= corr;
#pragma unroll
                for (int d = 0; d < 64; d++) o[d] *= corr;
                m = val;
            }
            float p = expf(val - m);
            l += p;
#pragma unroll
            for (int d = 0; d < 64; d += 4) {
                float4 vv = *(const float4*)&vs[kk][d];
                o[d]     = fmaf(p, vv.x, o[d]);
                o[d + 1] = fmaf(p, vv.y, o[d + 1]);
                o[d + 2] = fmaf(p, vv.z, o[d + 2]);
                o[d + 3] = fmaf(p, vv.w, o[d + 3]);
            }
        }
    }

    float inv = 1.0f / l;
    float* op = g_ao + (((size_t)b * SQ + qrow) * NH + h) * DKH;
#pragma unroll
    for (int d = 0; d < 64; d += 4) {
        float4 t;
        t.x = o[d] * inv; t.y = o[d + 1] * inv;
        t.z = o[d + 2] * inv; t.w = o[d + 3] * inv;
        *(float4*)(op + d) = t;
    }
}

// ---------------- launch ----------------------------------------------------
extern "C" void kernel_launch(void* const* d_in, const int* in_sizes, int n_in,
                              void* d_out, int out_size) {
    (void)in_sizes; (void)n_in; (void)out_size;
    const float* x    = (const float*)d_in[0];
    const int*   mask = (const int*)d_in[1];
    const float* pos  = (const float*)d_in[2];
    // d_in[3] = decoder_mask (always 1 for this problem; causal path hardcoded)
    const float* Wq = (const float*)d_in[4];
    const float* bq = (const float*)d_in[5];
    const float* Wk = (const float*)d_in[6];
    const float* bk = (const float*)d_in[7];
    const float* Wv = (const float*)d_in[8];
    const float* bv = (const float*)d_in[9];
    const float* Wo = (const float*)d_in[10];
    const float* bo = (const float*)d_in[11];
    float* out = (float*)d_out;

    float *pq, *pk, *pv, *pao;
    cudaGetSymbolAddress((void**)&pq,  g_q);
    cudaGetSymbolAddress((void**)&pk,  g_k);
    cudaGetSymbolAddress((void**)&pv,  g_v);
    cudaGetSymbolAddress((void**)&pao, g_ao);

    bern_kernel<<<NELEM / 256, 256>>>();

    dim3 gg(8, 32);   // N/128, M/128
    sgemm_relu_kernel<1><<<gg, 256>>>(x, Wq, bq, pq);
    sgemm_relu_kernel<1><<<gg, 256>>>(x, Wk, bk, pk);
    sgemm_relu_kernel<1><<<gg, 256>>>(x, Wv, bv, pv);

    dim3 ga(8, NH, NB);
    attn_kernel<<<ga, 128>>>(pos, mask);

    sgemm_relu_kernel<0><<<gg, 256>>>(pao, Wo, bo, out);
}

// round 3
// speedup vs baseline: 1.0715x; 1.0715x over previous
#include <cuda_runtime.h>
#include <math.h>

// Problem constants
#define NB 4
#define SQ 1024
#define DM 1024
#define NH 16
#define DKH 64
#define NKV (NB * NH * SQ * DKH)
#define NELEM 67108864u               // 4*16*1024*1024 bern elements

// ---------------- scratch (static device globals; no allocs) ----------------
__device__ float g_q[NKV];            // [b,h,s,d]
__device__ float g_k[NKV];
__device__ float g_v[NKV];
__device__ float g_ao[NB * SQ * NH * DKH];        // [b,q,h,d]
__device__ unsigned g_bern[NELEM / 32];           // packed bernoulli bits
__device__ float g_vsuf[64 * 32 * 64];            // suffix sums of V per (b*h, j, d)

// ---------------- threefry2x32, JAX partitionable mode ----------------------
__device__ __forceinline__ unsigned rotl32(unsigned x, int r) {
    return __funnelshift_l(x, x, r);
}

__global__ void __launch_bounds__(256) bern_kernel() {
    unsigned e = blockIdx.x * 256u + threadIdx.x;
    unsigned x0 = 0u;
    unsigned x1 = e;
    const unsigned ks1 = 42u;
    const unsigned ks2 = 0x1BD11BDAu ^ 42u;
    x0 += 0u; x1 += ks1;
#define TF_RND(r) { x0 += x1; x1 = rotl32(x1, (r)); x1 ^= x0; }
    TF_RND(13) TF_RND(15) TF_RND(26) TF_RND(6)
    x0 += ks1; x1 += ks2 + 1u;
    TF_RND(17) TF_RND(29) TF_RND(16) TF_RND(24)
    x0 += ks2; x1 += 0u + 2u;
    TF_RND(13) TF_RND(15) TF_RND(26) TF_RND(6)
    x0 += 0u; x1 += ks1 + 3u;
    TF_RND(17) TF_RND(29) TF_RND(16) TF_RND(24)
    x0 += ks1; x1 += ks2 + 4u;
    TF_RND(13) TF_RND(15) TF_RND(26) TF_RND(6)
    x0 += ks2; x1 += 0u + 5u;
#undef TF_RND
    unsigned bits = x0 ^ x1;
    unsigned keep = ((bits >> 9) < 2516583u) ? 1u : 0u;   // uniform < 0.3f
    unsigned w = __ballot_sync(0xffffffffu, keep != 0u);
    if ((threadIdx.x & 31u) == 0u) g_bern[e >> 5] = w;
}

// ---------------- tf32 helpers ----------------------------------------------
__device__ __forceinline__ unsigned f2tf(float x) {
    unsigned r;
    asm("cvt.rna.tf32.f32 %0, %1;" : "=r"(r) : "f"(x));
    return r;
}

__device__ __forceinline__ void mma_tf32(float c[4], const unsigned a[4], const unsigned b[2]) {
    asm volatile(
        "mma.sync.aligned.m16n8k8.row.col.f32.tf32.tf32.f32 "
        "{%0,%1,%2,%3}, {%4,%5,%6,%7}, {%8,%9}, {%0,%1,%2,%3};"
        : "+f"(c[0]), "+f"(c[1]), "+f"(c[2]), "+f"(c[3])
        : "r"(a[0]), "r"(a[1]), "r"(a[2]), "r"(a[3]), "r"(b[0]), "r"(b[1]));
}

// ---------------- tf32x3 MMA GEMM + bias + relu -----------------------------
// C[4096,1024] = relu(A @ W + bias); BM=128, BN=64, BK=16; 256 threads.
// SCATTER=1: write [b,h,s,d]; SCATTER=0: row-major.
#define ASTRIDE 136
#define BSTRIDE 72
template <int SCATTER>
__global__ void __launch_bounds__(256) mma_gemm_relu(
    const float* __restrict__ A, const float* __restrict__ W,
    const float* __restrict__ bias, float* __restrict__ out)
{
    __shared__ float Ah[16][ASTRIDE], Al[16][ASTRIDE];
    __shared__ float Bh[16][BSTRIDE], Bl[16][BSTRIDE];
    int tid = threadIdx.x;
    int lane = tid & 31, warp = tid >> 5;
    int wm = warp & 3, wn = warp >> 2;        // 4 x 2 warp grid
    int g = lane >> 2, tg = lane & 3;
    int m0 = blockIdx.y * 128, n0 = blockIdx.x * 64;

    float c[2][4][4];
#pragma unroll
    for (int mt = 0; mt < 2; mt++)
#pragma unroll
        for (int nt = 0; nt < 4; nt++)
#pragma unroll
            for (int i = 0; i < 4; i++) c[mt][nt][i] = 0.f;

    for (int kt = 0; kt < 1024; kt += 16) {
        // Load A tile 128x16, split hi/lo tf32
#pragma unroll
        for (int i = 0; i < 2; i++) {
            int f4 = tid + i * 256;
            int m = f4 >> 2, kq = (f4 & 3) * 4;
            float4 v = *(const float4*)(A + (size_t)(m0 + m) * 1024 + kt + kq);
            float vv[4] = {v.x, v.y, v.z, v.w};
#pragma unroll
            for (int j = 0; j < 4; j++) {
                float hf = __uint_as_float(f2tf(vv[j]));
                Ah[kq + j][m] = hf;
                Al[kq + j][m] = __uint_as_float(f2tf(vv[j] - hf));
            }
        }
        // Load B tile 16x64
        {
            int kr = tid >> 4, c4 = (tid & 15) * 4;
            float4 v = *(const float4*)(W + (size_t)(kt + kr) * 1024 + n0 + c4);
            float vv[4] = {v.x, v.y, v.z, v.w};
#pragma unroll
            for (int j = 0; j < 4; j++) {
                float hf = __uint_as_float(f2tf(vv[j]));
                Bh[kr][c4 + j] = hf;
                Bl[kr][c4 + j] = __uint_as_float(f2tf(vv[j] - hf));
            }
        }
        __syncthreads();

#pragma unroll
        for (int k8 = 0; k8 < 16; k8 += 8) {
            unsigned a_[2][2][4], b_[4][2][2];
#pragma unroll
            for (int mt = 0; mt < 2; mt++) {
                int mb = wm * 32 + mt * 16;
                a_[mt][0][0] = __float_as_uint(Ah[k8 + tg][mb + g]);
                a_[mt][0][1] = __float_as_uint(Ah[k8 + tg][mb + g + 8]);
                a_[mt][0][2] = __float_as_uint(Ah[k8 + tg + 4][mb + g]);
                a_[mt][0][3] = __float_as_uint(Ah[k8 + tg + 4][mb + g + 8]);
                a_[mt][1][0] = __float_as_uint(Al[k8 + tg][mb + g]);
                a_[mt][1][1] = __float_as_uint(Al[k8 + tg][mb + g + 8]);
                a_[mt][1][2] = __float_as_uint(Al[k8 + tg + 4][mb + g]);
                a_[mt][1][3] = __float_as_uint(Al[k8 + tg + 4][mb + g + 8]);
            }
#pragma unroll
            for (int nt = 0; nt < 4; nt++) {
                int nb = wn * 32 + nt * 8;
                b_[nt][0][0] = __float_as_uint(Bh[k8 + tg][nb + g]);
                b_[nt][0][1] = __float_as_uint(Bh[k8 + tg + 4][nb + g]);
                b_[nt][1][0] = __float_as_uint(Bl[k8 + tg][nb + g]);
                b_[nt][1][1] = __float_as_uint(Bl[k8 + tg + 4][nb + g]);
            }
#pragma unroll
            for (int mt = 0; mt < 2; mt++)
#pragma unroll
                for (int nt = 0; nt < 4; nt++) {
                    mma_tf32(c[mt][nt], a_[mt][0], b_[nt][0]);   // hi*hi
                    mma_tf32(c[mt][nt], a_[mt][0], b_[nt][1]);   // hi*lo
                    mma_tf32(c[mt][nt], a_[mt][1], b_[nt][0]);   // lo*hi
                }
        }
        __syncthreads();
    }

#pragma unroll
    for (int mt = 0; mt < 2; mt++)
#pragma unroll
        for (int nt = 0; nt < 4; nt++)
#pragma unroll
            for (int ci = 0; ci < 4; ci++) {
                int row = m0 + wm * 32 + mt * 16 + g + (ci >> 1) * 8;
                int col = n0 + wn * 32 + nt * 8 + tg * 2 + (ci & 1);
                float v = fmaxf(c[mt][nt][ci] + bias[col], 0.f);
                if (SCATTER) {
                    int b = row >> 10, s = row & 1023;
                    int h = col >> 6, d = col & 63;
                    out[(((size_t)(b * NH + h)) * SQ + s) * DKH + d] = v;
                } else {
                    out[(size_t)row * 1024 + col] = v;
                }
            }
}

// ---------------- V suffix sums ---------------------------------------------
// g_vsuf[bh][j][d] = sum_{s >= 32j} v[bh][s][d]
__global__ void __launch_bounds__(1024) vsuf_kernel() {
    int bh = blockIdx.x;
    __shared__ float part[32][64];
    int d = threadIdx.x & 63;
    int jj = threadIdx.x >> 6;    // 0..15
#pragma unroll
    for (int p = 0; p < 2; p++) {
        int j = p * 16 + jj;
        const float* vp = g_v + ((size_t)bh * 1024 + j * 32) * 64 + d;
        float sum = 0.f;
#pragma unroll
        for (int s = 0; s < 32; s++) sum += vp[s * 64];
        part[j][d] = sum;
    }
    __syncthreads();
    if (threadIdx.x < 64) {
        float run = 0.f;
        for (int j = 31; j >= 0; j--) {
            run += part[j][threadIdx.x];
            g_vsuf[((size_t)bh * 32 + j) * 64 + threadIdx.x] = run;
        }
    }
}

// ---------------- fused attention (flash-style, causal tail-skip) -----------
__global__ void __launch_bounds__(128) attn_kernel(
    const float* __restrict__ pos, const int* __restrict__ mask)
{
    int qb = blockIdx.x, h = blockIdx.y, b = blockIdx.z;
    int tid = threadIdx.x;
    int qrow = qb * 128 + tid;

    __shared__ float ks[32][64];
    __shared__ float vs[32][64];
    __shared__ float ps[128][33];

    size_t bh = (size_t)(b * NH + h);
    const float* qp = g_q + (bh * SQ + qrow) * DKH;

    float q[64], o[64];
#pragma unroll
    for (int d = 0; d < 64; d += 4) {
        float4 t = *(const float4*)(qp + d);
        q[d] = t.x; q[d + 1] = t.y; q[d + 2] = t.z; q[d + 3] = t.w;
        o[d] = 0.f; o[d + 1] = 0.f; o[d + 2] = 0.f; o[d + 3] = 0.f;
    }
    float m = -INFINITY, l = 0.f;

    const float4* kbase = (const float4*)(g_k + bh * SQ * DKH);
    const float4* vbase = (const float4*)(g_v + bh * SQ * DKH);
    unsigned bernbase = (unsigned)(bh * SQ + qrow) * 32u;

    int kb_end = (qb + 1) * 128;   // block's max needed keys (causal)

    for (int kb = 0; kb < kb_end; kb += 32) {
        __syncthreads();
        {
            const float4* kg4 = kbase + kb * 16;
            const float4* vg4 = vbase + kb * 16;
            float4* ksm = (float4*)&ks[0][0];
            float4* vsm = (float4*)&vs[0][0];
#pragma unroll
            for (int i = 0; i < 4; i++) {
                ksm[tid + i * 128] = kg4[tid + i * 128];
                vsm[tid + i * 128] = vg4[tid + i * 128];
            }
#pragma unroll
            for (int i = 0; i < 32; i++) {
                int idx = tid + i * 128;
                int r = idx >> 5, cc = idx & 31;
                ps[r][cc] = pos[((size_t)b * SQ + qb * 128 + r) * SQ + kb + cc];
            }
        }
        __syncthreads();

        if (kb <= qrow) {
            unsigned bw = g_bern[bernbase + (kb >> 5)];
#pragma unroll
            for (int half = 0; half < 2; half++) {
                float s[16];
#pragma unroll
                for (int j = 0; j < 16; j++) {
                    int kk = half * 16 + j;
                    float s0 = 0.f, s1 = 0.f, s2 = 0.f, s3 = 0.f;
#pragma unroll
                    for (int d = 0; d < 64; d += 16) {
                        float4 k0 = *(const float4*)&ks[kk][d];
                        float4 k1 = *(const float4*)&ks[kk][d + 4];
                        float4 k2 = *(const float4*)&ks[kk][d + 8];
                        float4 k3 = *(const float4*)&ks[kk][d + 12];
                        s0 = fmaf(q[d], k0.x, s0);      s0 = fmaf(q[d + 1], k0.y, s0);
                        s0 = fmaf(q[d + 2], k0.z, s0);  s0 = fmaf(q[d + 3], k0.w, s0);
                        s1 = fmaf(q[d + 4], k1.x, s1);  s1 = fmaf(q[d + 5], k1.y, s1);
                        s1 = fmaf(q[d + 6], k1.z, s1);  s1 = fmaf(q[d + 7], k1.w, s1);
                        s2 = fmaf(q[d + 8], k2.x, s2);  s2 = fmaf(q[d + 9], k2.y, s2);
                        s2 = fmaf(q[d + 10], k2.z, s2); s2 = fmaf(q[d + 11], k2.w, s2);
                        s3 = fmaf(q[d + 12], k3.x, s3); s3 = fmaf(q[d + 13], k3.y, s3);
                        s3 = fmaf(q[d + 14], k3.z, s3); s3 = fmaf(q[d + 15], k3.w, s3);
                    }
                    float val = ((s0 + s1) + (s2 + s3)) * 0.125f + ps[tid][kk];
                    if ((bw >> kk) & 1u) val = val + (-1e9f);
                    int kg = kb + kk;
                    if (mask[b * SQ + kg] != 0) val = -1e9f;
                    if (kg > qrow) val = -1e9f;
                    s[j] = val;
                }
                float vmax = s[0];
#pragma unroll
                for (int j = 1; j < 16; j++) vmax = fmaxf(vmax, s[j]);
                if (vmax > m) {
                    float corr = __expf(m - vmax);
                    l *= corr;
#pragma unroll
                    for (int d = 0; d < 64; d++) o[d] *= corr;
                    m = vmax;
                }
#pragma unroll
                for (int j = 0; j < 16; j++) {
                    float p = __expf(s[j] - m);
                    l += p;
                    int kk = half * 16 + j;
#pragma unroll
                    for (int d = 0; d < 64; d += 4) {
                        float4 vv = *(const float4*)&vs[kk][d];
                        o[d]     = fmaf(p, vv.x, o[d]);
                        o[d + 1] = fmaf(p, vv.y, o[d + 1]);
                        o[d + 2] = fmaf(p, vv.z, o[d + 2]);
                        o[d + 3] = fmaf(p, vv.w, o[d + 3]);
                    }
                }
            }
        }
    }

    // causal tail: all keys kg > qrow have val == -1e9 exactly
    int jt = (qrow >> 5) + 1;
    if (jt < 32) {
        float pt = __expf(-1e9f - m);
        l += pt * (float)(1024 - jt * 32);
        if (pt > 0.f) {
            const float* sp = g_vsuf + ((size_t)(bh * 32 + jt)) * 64;
#pragma unroll
            for (int d = 0; d < 64; d++) o[d] = fmaf(pt, sp[d], o[d]);
        }
    }

    float inv = 1.0f / l;
    float* op = g_ao + (((size_t)b * SQ + qrow) * NH + h) * DKH;
#pragma unroll
    for (int d = 0; d < 64; d += 4) {
        float4 t;
        t.x = o[d] * inv; t.y = o[d + 1] * inv;
        t.z = o[d + 2] * inv; t.w = o[d + 3] * inv;
        *(float4*)(op + d) = t;
    }
}

// ---------------- launch ----------------------------------------------------
extern "C" void kernel_launch(void* const* d_in, const int* in_sizes, int n_in,
                              void* d_out, int out_size) {
    (void)in_sizes; (void)n_in; (void)out_size;
    const float* x    = (const float*)d_in[0];
    const int*   mask = (const int*)d_in[1];
    const float* pos  = (const float*)d_in[2];
    const float* Wq = (const float*)d_in[4];
    const float* bq = (const float*)d_in[5];
    const float* Wk = (const float*)d_in[6];
    const float* bk = (const float*)d_in[7];
    const float* Wv = (const float*)d_in[8];
    const float* bv = (const float*)d_in[9];
    const float* Wo = (const float*)d_in[10];
    const float* bo = (const float*)d_in[11];
    float* out = (float*)d_out;

    float *pq, *pk, *pv, *pao;
    cudaGetSymbolAddress((void**)&pq,  g_q);
    cudaGetSymbolAddress((void**)&pk,  g_k);
    cudaGetSymbolAddress((void**)&pv,  g_v);
    cudaGetSymbolAddress((void**)&pao, g_ao);

    bern_kernel<<<NELEM / 256, 256>>>();

    dim3 gg(16, 32);   // N/64, M/128
    mma_gemm_relu<1><<<gg, 256>>>(x, Wq, bq, pq);
    mma_gemm_relu<1><<<gg, 256>>>(x, Wk, bk, pk);
    mma_gemm_relu<1><<<gg, 256>>>(x, Wv, bv, pv);

    vsuf_kernel<<<64, 1024>>>();

    dim3 ga(8, NH, NB);
    attn_kernel<<<ga, 128>>>(pos, mask);

    mma_gemm_relu<0><<<gg, 256>>>(pao, Wo, bo, out);
}

// round 4
// speedup vs baseline: 1.2365x; 1.1540x over previous
#include <cuda_runtime.h>
#include <math.h>

#define NB 4
#define SQ 1024
#define DM 1024
#define NH 16
#define DKH 64
#define NKV (NB * NH * SQ * DKH)
#define NELEM 67108864u

// ---------------- scratch ----------------------------------------------------
__device__ float g_q[NKV];            // [b,h,s,d]
__device__ float g_k[NKV];
__device__ float g_v[NKV];
__device__ float g_ao[NB * SQ * NH * DKH];        // [b,q,h,d]
__device__ unsigned g_bern[NELEM / 32];
__device__ float g_vsuf[64 * 32 * 64];

// ---------------- threefry2x32 (JAX partitionable, key=(0,42)) --------------
__device__ __forceinline__ unsigned rotl32(unsigned x, int r) {
    return __funnelshift_l(x, x, r);
}

__global__ void __launch_bounds__(256) bern_kernel() {
    unsigned e = blockIdx.x * 256u + threadIdx.x;
    // dead-bit skip: bits for kg>qrow are overwritten by causal mask, never read
    unsigned qr = (e >> 10) & 1023u;
    unsigned kg0 = e & 992u;          // 32-aligned key index within row
    if (kg0 > qr) return;             // warp-uniform exit

    unsigned x0 = 0u;
    unsigned x1 = e;
    const unsigned ks1 = 42u;
    const unsigned ks2 = 0x1BD11BDAu ^ 42u;
    x1 += ks1;
#define TF_RND(r) { x0 += x1; x1 = rotl32(x1, (r)); x1 ^= x0; }
    TF_RND(13) TF_RND(15) TF_RND(26) TF_RND(6)
    x0 += ks1; x1 += ks2 + 1u;
    TF_RND(17) TF_RND(29) TF_RND(16) TF_RND(24)
    x0 += ks2; x1 += 0u + 2u;
    TF_RND(13) TF_RND(15) TF_RND(26) TF_RND(6)
    x0 += 0u; x1 += ks1 + 3u;
    TF_RND(17) TF_RND(29) TF_RND(16) TF_RND(24)
    x0 += ks1; x1 += ks2 + 4u;
    TF_RND(13) TF_RND(15) TF_RND(26) TF_RND(6)
    x0 += ks2; x1 += 0u + 5u;
#undef TF_RND
    unsigned bits = x0 ^ x1;
    unsigned keep = ((bits >> 9) < 2516583u) ? 1u : 0u;    // uniform < 0.3f
    unsigned w = __ballot_sync(0xffffffffu, keep != 0u);
    if ((threadIdx.x & 31u) == 0u) g_bern[e >> 5] = w;
}

// ---------------- tf32 helpers ----------------------------------------------
__device__ __forceinline__ unsigned f2tf(float x) {
    unsigned r;
    asm("cvt.rna.tf32.f32 %0, %1;" : "=r"(r) : "f"(x));
    return r;
}

__device__ __forceinline__ void mma_tf32(float c[4], const unsigned a[4], const unsigned b[2]) {
    asm volatile(
        "mma.sync.aligned.m16n8k8.row.col.f32.tf32.tf32.f32 "
        "{%0,%1,%2,%3}, {%4,%5,%6,%7}, {%8,%9}, {%0,%1,%2,%3};"
        : "+f"(c[0]), "+f"(c[1]), "+f"(c[2]), "+f"(c[3])
        : "r"(a[0]), "r"(a[1]), "r"(a[2]), "r"(a[3]), "r"(b[0]), "r"(b[1]));
}

// ---------------- tf32x3 double-buffered GEMM + bias + relu -----------------
// C[4096,1024] = relu(A @ W + bias). BM=128, BN=64, BK=16, 2-stage ping-pong.
#define AOFF 2176   // 16*136 floats per A stage
#define BOFF 1152   // 16*72 floats per B stage
#define SMEM_GEMM_BYTES ((2 * AOFF * 2 + 2 * BOFF * 2) * 4)   // 53248

__device__ __forceinline__ void cvt_store_tile(
    float* Ahb, float* Alb, float* Bhb, float* Blb,
    int tid, const float4* av, float4 bv4)
{
#pragma unroll
    for (int i = 0; i < 2; i++) {
        int f4 = tid + i * 256;
        int m = f4 >> 2, kq = (f4 & 3) * 4;
        float vv[4] = {av[i].x, av[i].y, av[i].z, av[i].w};
#pragma unroll
        for (int j = 0; j < 4; j++) {
            float hf = __uint_as_float(f2tf(vv[j]));
            Ahb[(kq + j) * 136 + m] = hf;
            Alb[(kq + j) * 136 + m] = __uint_as_float(f2tf(vv[j] - hf));
        }
    }
    {
        int kr = tid >> 4, c4 = (tid & 15) * 4;
        float vv[4] = {bv4.x, bv4.y, bv4.z, bv4.w};
#pragma unroll
        for (int j = 0; j < 4; j++) {
            float hf = __uint_as_float(f2tf(vv[j]));
            Bhb[kr * 72 + c4 + j] = hf;
            Blb[kr * 72 + c4 + j] = __uint_as_float(f2tf(vv[j] - hf));
        }
    }
}

template <int SCATTER>
__device__ __forceinline__ void gemm_body(
    const float* __restrict__ A, const float* __restrict__ W,
    const float* __restrict__ bias, float* __restrict__ out)
{
    extern __shared__ float sm[];
    float* Ah = sm;                       // [2][16][136]
    float* Al = sm + 2 * AOFF;
    float* Bh = sm + 4 * AOFF;            // [2][16][72]
    float* Bl = sm + 4 * AOFF + 2 * BOFF;

    int tid = threadIdx.x;
    int lane = tid & 31, warp = tid >> 5;
    int wm = warp & 3, wn = warp >> 2;    // 4 x 2 warp grid
    int g = lane >> 2, tg = lane & 3;
    int m0 = blockIdx.y * 128, n0 = blockIdx.x * 64;

    float c[2][4][4];
#pragma unroll
    for (int mt = 0; mt < 2; mt++)
#pragma unroll
        for (int nt = 0; nt < 4; nt++)
#pragma unroll
            for (int i = 0; i < 4; i++) c[mt][nt][i] = 0.f;

    // preload stage 0
    {
        float4 av[2], bv4;
#pragma unroll
        for (int i = 0; i < 2; i++) {
            int f4 = tid + i * 256;
            int m = f4 >> 2, kq = (f4 & 3) * 4;
            av[i] = *(const float4*)(A + (size_t)(m0 + m) * 1024 + kq);
        }
        int kr = tid >> 4, c4 = (tid & 15) * 4;
        bv4 = *(const float4*)(W + (size_t)kr * 1024 + n0 + c4);
        cvt_store_tile(Ah, Al, Bh, Bl, tid, av, bv4);
    }
    __syncthreads();

    int buf = 0;
    for (int kt = 0; kt < 1024; kt += 16) {
        float4 av[2], bv4;
        bool has_next = (kt + 16) < 1024;
        if (has_next) {
#pragma unroll
            for (int i = 0; i < 2; i++) {
                int f4 = tid + i * 256;
                int m = f4 >> 2, kq = (f4 & 3) * 4;
                av[i] = *(const float4*)(A + (size_t)(m0 + m) * 1024 + kt + 16 + kq);
            }
            int kr = tid >> 4, c4 = (tid & 15) * 4;
            bv4 = *(const float4*)(W + (size_t)(kt + 16 + kr) * 1024 + n0 + c4);
        }

        const float* ah = Ah + buf * AOFF;
        const float* al = Al + buf * AOFF;
        const float* bh = Bh + buf * BOFF;
        const float* bl = Bl + buf * BOFF;
#pragma unroll
        for (int k8 = 0; k8 < 16; k8 += 8) {
            unsigned a_[2][2][4], b_[4][2][2];
#pragma unroll
            for (int mt = 0; mt < 2; mt++) {
                int mb = wm * 32 + mt * 16;
                a_[mt][0][0] = __float_as_uint(ah[(k8 + tg) * 136 + mb + g]);
                a_[mt][0][1] = __float_as_uint(ah[(k8 + tg) * 136 + mb + g + 8]);
                a_[mt][0][2] = __float_as_uint(ah[(k8 + tg + 4) * 136 + mb + g]);
                a_[mt][0][3] = __float_as_uint(ah[(k8 + tg + 4) * 136 + mb + g + 8]);
                a_[mt][1][0] = __float_as_uint(al[(k8 + tg) * 136 + mb + g]);
                a_[mt][1][1] = __float_as_uint(al[(k8 + tg) * 136 + mb + g + 8]);
                a_[mt][1][2] = __float_as_uint(al[(k8 + tg + 4) * 136 + mb + g]);
                a_[mt][1][3] = __float_as_uint(al[(k8 + tg + 4) * 136 + mb + g + 8]);
            }
#pragma unroll
            for (int nt = 0; nt < 4; nt++) {
                int nb = wn * 32 + nt * 8;
                b_[nt][0][0] = __float_as_uint(bh[(k8 + tg) * 72 + nb + g]);
                b_[nt][0][1] = __float_as_uint(bh[(k8 + tg + 4) * 72 + nb + g]);
                b_[nt][1][0] = __float_as_uint(bl[(k8 + tg) * 72 + nb + g]);
                b_[nt][1][1] = __float_as_uint(bl[(k8 + tg + 4) * 72 + nb + g]);
            }
#pragma unroll
            for (int mt = 0; mt < 2; mt++)
#pragma unroll
                for (int nt = 0; nt < 4; nt++) {
                    mma_tf32(c[mt][nt], a_[mt][0], b_[nt][0]);
                    mma_tf32(c[mt][nt], a_[mt][0], b_[nt][1]);
                    mma_tf32(c[mt][nt], a_[mt][1], b_[nt][0]);
                }
        }

        if (has_next) {
            int nbuf = buf ^ 1;
            cvt_store_tile(Ah + nbuf * AOFF, Al + nbuf * AOFF,
                           Bh + nbuf * BOFF, Bl + nbuf * BOFF, tid, av, bv4);
            __syncthreads();
            buf = nbuf;
        }
    }

#pragma unroll
    for (int mt = 0; mt < 2; mt++)
#pragma unroll
        for (int nt = 0; nt < 4; nt++)
#pragma unroll
            for (int ci = 0; ci < 4; ci++) {
                int row = m0 + wm * 32 + mt * 16 + g + (ci >> 1) * 8;
                int col = n0 + wn * 32 + nt * 8 + tg * 2 + (ci & 1);
                float v = fmaxf(c[mt][nt][ci] + bias[col], 0.f);
                if (SCATTER) {
                    int b = row >> 10, s = row & 1023;
                    int h = col >> 6, d = col & 63;
                    out[(((size_t)(b * NH + h)) * SQ + s) * DKH + d] = v;
                } else {
                    out[(size_t)row * 1024 + col] = v;
                }
            }
}

__global__ void __launch_bounds__(256) qkv_gemm_kernel(
    const float* __restrict__ x,
    const float* __restrict__ Wq, const float* __restrict__ bq, float* __restrict__ oq,
    const float* __restrict__ Wk, const float* __restrict__ bk, float* __restrict__ ok,
    const float* __restrict__ Wv, const float* __restrict__ bv, float* __restrict__ ov)
{
    const float* W; const float* bias; float* out;
    if (blockIdx.z == 0)      { W = Wq; bias = bq; out = oq; }
    else if (blockIdx.z == 1) { W = Wk; bias = bk; out = ok; }
    else                      { W = Wv; bias = bv; out = ov; }
    gemm_body<1>(x, W, bias, out);
}

__global__ void __launch_bounds__(256) out_gemm_kernel(
    const float* __restrict__ A, const float* __restrict__ W,
    const float* __restrict__ bias, float* __restrict__ out)
{
    gemm_body<0>(A, W, bias, out);
}

// ---------------- V suffix sums ---------------------------------------------
__global__ void __launch_bounds__(1024) vsuf_kernel() {
    int bh = blockIdx.x;
    __shared__ float part[32][64];
    int d = threadIdx.x & 63;
    int jj = threadIdx.x >> 6;
#pragma unroll
    for (int p = 0; p < 2; p++) {
        int j = p * 16 + jj;
        const float* vp = g_v + ((size_t)bh * 1024 + j * 32) * 64 + d;
        float sum = 0.f;
#pragma unroll
        for (int s = 0; s < 32; s++) sum += vp[s * 64];
        part[j][d] = sum;
    }
    __syncthreads();
    if (threadIdx.x < 64) {
        float run = 0.f;
        for (int j = 31; j >= 0; j--) {
            run += part[j][threadIdx.x];
            g_vsuf[((size_t)bh * 32 + j) * 64 + threadIdx.x] = run;
        }
    }
}

// ---------------- fused attention (flash-style, causal tail-skip) -----------
__global__ void __launch_bounds__(128) attn_kernel(
    const float* __restrict__ pos, const int* __restrict__ mask)
{
    int qb = blockIdx.x, h = blockIdx.y, b = blockIdx.z;
    int tid = threadIdx.x;
    int qrow = qb * 128 + tid;

    __shared__ float ks[32][64];
    __shared__ float vs[32][64];
    __shared__ float ps[128][33];

    size_t bh = (size_t)(b * NH + h);
    const float* qp = g_q + (bh * SQ + qrow) * DKH;

    float q[64], o[64];
#pragma unroll
    for (int d = 0; d < 64; d += 4) {
        float4 t = *(const float4*)(qp + d);
        q[d] = t.x; q[d + 1] = t.y; q[d + 2] = t.z; q[d + 3] = t.w;
        o[d] = 0.f; o[d + 1] = 0.f; o[d + 2] = 0.f; o[d + 3] = 0.f;
    }
    float m = -INFINITY, l = 0.f;

    const float4* kbase = (const float4*)(g_k + bh * SQ * DKH);
    const float4* vbase = (const float4*)(g_v + bh * SQ * DKH);
    unsigned bernbase = (unsigned)(bh * SQ + qrow) * 32u;

    int kb_end = (qb + 1) * 128;

    for (int kb = 0; kb < kb_end; kb += 32) {
        __syncthreads();
        {
            const float4* kg4 = kbase + kb * 16;
            const float4* vg4 = vbase + kb * 16;
            float4* ksm = (float4*)&ks[0][0];
            float4* vsm = (float4*)&vs[0][0];
#pragma unroll
            for (int i = 0; i < 4; i++) {
                ksm[tid + i * 128] = kg4[tid + i * 128];
                vsm[tid + i * 128] = vg4[tid + i * 128];
            }
#pragma unroll
            for (int i = 0; i < 32; i++) {
                int idx = tid + i * 128;
                int r = idx >> 5, cc = idx & 31;
                ps[r][cc] = pos[((size_t)b * SQ + qb * 128 + r) * SQ + kb + cc];
            }
        }
        __syncthreads();

        if (kb <= qrow) {
            unsigned bw = g_bern[bernbase + (kb >> 5)];
            unsigned mw = __ballot_sync(0xffffffffu,
                                        mask[b * SQ + kb + (tid & 31)] != 0);
#pragma unroll
            for (int half = 0; half < 2; half++) {
                float s[16];
#pragma unroll
                for (int j = 0; j < 16; j++) {
                    int kk = half * 16 + j;
                    float s0 = 0.f, s1 = 0.f, s2 = 0.f, s3 = 0.f;
#pragma unroll
                    for (int d = 0; d < 64; d += 16) {
                        float4 k0 = *(const float4*)&ks[kk][d];
                        float4 k1 = *(const float4*)&ks[kk][d + 4];
                        float4 k2 = *(const float4*)&ks[kk][d + 8];
                        float4 k3 = *(const float4*)&ks[kk][d + 12];
                        s0 = fmaf(q[d], k0.x, s0);      s0 = fmaf(q[d + 1], k0.y, s0);
                        s0 = fmaf(q[d + 2], k0.z, s0);  s0 = fmaf(q[d + 3], k0.w, s0);
                        s1 = fmaf(q[d + 4], k1.x, s1);  s1 = fmaf(q[d + 5], k1.y, s1);
                        s1 = fmaf(q[d + 6], k1.z, s1);  s1 = fmaf(q[d + 7], k1.w, s1);
                        s2 = fmaf(q[d + 8], k2.x, s2);  s2 = fmaf(q[d + 9], k2.y, s2);
                        s2 = fmaf(q[d + 10], k2.z, s2); s2 = fmaf(q[d + 11], k2.w, s2);
                        s3 = fmaf(q[d + 12], k3.x, s3); s3 = fmaf(q[d + 13], k3.y, s3);
                        s3 = fmaf(q[d + 14], k3.z, s3); s3 = fmaf(q[d + 15], k3.w, s3);
                    }
                    float val = ((s0 + s1) + (s2 + s3)) * 0.125f + ps[tid][kk];
                    if ((bw >> kk) & 1u) val = val + (-1e9f);
                    int kg = kb + kk;
                    if (((mw >> kk) & 1u) | (unsigned)(kg > qrow)) val = -1e9f;
                    s[j] = val;
                }
                float vmax = s[0];
#pragma unroll
                for (int j = 1; j < 16; j++) vmax = fmaxf(vmax, s[j]);
                if (vmax > m) {
                    float corr = __expf(m - vmax);
                    l *= corr;
#pragma unroll
                    for (int d = 0; d < 64; d++) o[d] *= corr;
                    m = vmax;
                }
#pragma unroll
                for (int j = 0; j < 16; j++) {
                    float p = __expf(s[j] - m);
                    l += p;
                    int kk = half * 16 + j;
#pragma unroll
                    for (int d = 0; d < 64; d += 4) {
                        float4 vv = *(const float4*)&vs[kk][d];
                        o[d]     = fmaf(p, vv.x, o[d]);
                        o[d + 1] = fmaf(p, vv.y, o[d + 1]);
                        o[d + 2] = fmaf(p, vv.z, o[d + 2]);
                        o[d + 3] = fmaf(p, vv.w, o[d + 3]);
                    }
                }
            }
        }
    }

    // causal tail: keys kg > qrow all have val == -1e9 exactly
    int jt = (qrow >> 5) + 1;
    if (jt < 32) {
        float pt = __expf(-1e9f - m);
        l += pt * (float)(1024 - jt * 32);
        if (pt > 0.f) {
            const float* sp = g_vsuf + ((size_t)(bh * 32 + jt)) * 64;
#pragma unroll
            for (int d = 0; d < 64; d++) o[d] = fmaf(pt, sp[d], o[d]);
        }
    }

    float inv = 1.0f / l;
    float* op = g_ao + (((size_t)b * SQ + qrow) * NH + h) * DKH;
#pragma unroll
    for (int d = 0; d < 64; d += 4) {
        float4 t;
        t.x = o[d] * inv; t.y = o[d + 1] * inv;
        t.z = o[d + 2] * inv; t.w = o[d + 3] * inv;
        *(float4*)(op + d) = t;
    }
}

// ---------------- launch ----------------------------------------------------
extern "C" void kernel_launch(void* const* d_in, const int* in_sizes, int n_in,
                              void* d_out, int out_size) {
    (void)in_sizes; (void)n_in; (void)out_size;
    const float* x    = (const float*)d_in[0];
    const int*   mask = (const int*)d_in[1];
    const float* pos  = (const float*)d_in[2];
    const float* Wq = (const float*)d_in[4];
    const float* bq = (const float*)d_in[5];
    const float* Wk = (const float*)d_in[6];
    const float* bk = (const float*)d_in[7];
    const float* Wv = (const float*)d_in[8];
    const float* bv = (const float*)d_in[9];
    const float* Wo = (const float*)d_in[10];
    const float* bo = (const float*)d_in[11];
    float* out = (float*)d_out;

    float *pq, *pk, *pv, *pao;
    cudaGetSymbolAddress((void**)&pq,  g_q);
    cudaGetSymbolAddress((void**)&pk,  g_k);
    cudaGetSymbolAddress((void**)&pv,  g_v);
    cudaGetSymbolAddress((void**)&pao, g_ao);

    static int smem_set = 0;
    if (!smem_set) {
        cudaFuncSetAttribute(qkv_gemm_kernel,
            cudaFuncAttributeMaxDynamicSharedMemorySize, SMEM_GEMM_BYTES);
        cudaFuncSetAttribute(out_gemm_kernel,
            cudaFuncAttributeMaxDynamicSharedMemorySize, SMEM_GEMM_BYTES);
        smem_set = 1;
    }

    bern_kernel<<<NELEM / 256, 256>>>();

    dim3 gg(16, 32, 3);   // N/64, M/128, {q,k,v}
    qkv_gemm_kernel<<<gg, 256, SMEM_GEMM_BYTES>>>(
        x, Wq, bq, pq, Wk, bk, pk, Wv, bv, pv);

    vsuf_kernel<<<64, 1024>>>();

    dim3 ga(8, NH, NB);
    attn_kernel<<<ga, 128>>>(pos, mask);

    dim3 go(16, 32, 1);
    out_gemm_kernel<<<go, 256, SMEM_GEMM_BYTES>>>(pao, Wo, bo, out);
}

// round 5
// speedup vs baseline: 1.2929x; 1.0456x over previous
#include <cuda_runtime.h>
#include <math.h>

#define NB 4
#define SQ 1024
#define DM 1024
#define NH 16
#define DKH 64
#define NKV (NB * NH * SQ * DKH)
#define NELEM 67108864u

// ---------------- scratch ----------------------------------------------------
__device__ float g_q[NKV];            // [b,h,s,d]
__device__ float g_k[NKV];
__device__ float g_v[NKV];
__device__ float g_ao[NB * SQ * NH * DKH];        // [b,q,h,d]
__device__ unsigned g_bern[NELEM / 32];
__device__ float g_vsuf[64 * 32 * 64];

// ---------------- threefry2x32 (JAX partitionable, key=(0,42)) --------------
__device__ __forceinline__ unsigned rotl32(unsigned x, int r) {
    return __funnelshift_l(x, x, r);
}

__global__ void __launch_bounds__(256) bern_kernel() {
    unsigned e = blockIdx.x * 256u + threadIdx.x;
    // dead-bit skip: bits for kg>qrow are overwritten by causal mask, never read
    unsigned qr = (e >> 10) & 1023u;
    unsigned kg0 = e & 992u;
    if (kg0 > qr) return;             // warp-uniform exit

    unsigned x0 = 0u;
    unsigned x1 = e;
    const unsigned ks1 = 42u;
    const unsigned ks2 = 0x1BD11BDAu ^ 42u;
    x1 += ks1;
#define TF_RND(r) { x0 += x1; x1 = rotl32(x1, (r)); x1 ^= x0; }
    TF_RND(13) TF_RND(15) TF_RND(26) TF_RND(6)
    x0 += ks1; x1 += ks2 + 1u;
    TF_RND(17) TF_RND(29) TF_RND(16) TF_RND(24)
    x0 += ks2; x1 += 0u + 2u;
    TF_RND(13) TF_RND(15) TF_RND(26) TF_RND(6)
    x0 += 0u; x1 += ks1 + 3u;
    TF_RND(17) TF_RND(29) TF_RND(16) TF_RND(24)
    x0 += ks1; x1 += ks2 + 4u;
    TF_RND(13) TF_RND(15) TF_RND(26) TF_RND(6)
    x0 += ks2; x1 += 0u + 5u;
#undef TF_RND
    unsigned bits = x0 ^ x1;
    unsigned keep = ((bits >> 9) < 2516583u) ? 1u : 0u;    // uniform < 0.3f
    unsigned w = __ballot_sync(0xffffffffu, keep != 0u);
    if ((threadIdx.x & 31u) == 0u) g_bern[e >> 5] = w;
}

// ---------------- tf32 helpers ----------------------------------------------
__device__ __forceinline__ unsigned f2tf(float x) {
    unsigned r;
    asm("cvt.rna.tf32.f32 %0, %1;" : "=r"(r) : "f"(x));
    return r;
}

__device__ __forceinline__ void mma_tf32(float c[4], const unsigned a[4], const unsigned b[2]) {
    asm volatile(
        "mma.sync.aligned.m16n8k8.row.col.f32.tf32.tf32.f32 "
        "{%0,%1,%2,%3}, {%4,%5,%6,%7}, {%8,%9}, {%0,%1,%2,%3};"
        : "+f"(c[0]), "+f"(c[1]), "+f"(c[2]), "+f"(c[3])
        : "r"(a[0]), "r"(a[1]), "r"(a[2]), "r"(a[3]), "r"(b[0]), "r"(b[1]));
}

// ---------------- tf32x3 double-buffered GEMM + bias + relu -----------------
#define AOFF 2176
#define BOFF 1152
#define SMEM_GEMM_BYTES ((2 * AOFF * 2 + 2 * BOFF * 2) * 4)   // 53248

__device__ __forceinline__ void cvt_store_tile(
    float* Ahb, float* Alb, float* Bhb, float* Blb,
    int tid, const float4* av, float4 bv4)
{
#pragma unroll
    for (int i = 0; i < 2; i++) {
        int f4 = tid + i * 256;
        int m = f4 >> 2, kq = (f4 & 3) * 4;
        float vv[4] = {av[i].x, av[i].y, av[i].z, av[i].w};
#pragma unroll
        for (int j = 0; j < 4; j++) {
            float hf = __uint_as_float(f2tf(vv[j]));
            Ahb[(kq + j) * 136 + m] = hf;
            Alb[(kq + j) * 136 + m] = __uint_as_float(f2tf(vv[j] - hf));
        }
    }
    {
        int kr = tid >> 4, c4 = (tid & 15) * 4;
        float vv[4] = {bv4.x, bv4.y, bv4.z, bv4.w};
#pragma unroll
        for (int j = 0; j < 4; j++) {
            float hf = __uint_as_float(f2tf(vv[j]));
            Bhb[kr * 72 + c4 + j] = hf;
            Blb[kr * 72 + c4 + j] = __uint_as_float(f2tf(vv[j] - hf));
        }
    }
}

template <int SCATTER>
__device__ __forceinline__ void gemm_body(
    const float* __restrict__ A, const float* __restrict__ W,
    const float* __restrict__ bias, float* __restrict__ out)
{
    extern __shared__ float sm[];
    float* Ah = sm;
    float* Al = sm + 2 * AOFF;
    float* Bh = sm + 4 * AOFF;
    float* Bl = sm + 4 * AOFF + 2 * BOFF;

    int tid = threadIdx.x;
    int lane = tid & 31, warp = tid >> 5;
    int wm = warp & 3, wn = warp >> 2;
    int g = lane >> 2, tg = lane & 3;
    int m0 = blockIdx.y * 128, n0 = blockIdx.x * 64;

    float c[2][4][4];
#pragma unroll
    for (int mt = 0; mt < 2; mt++)
#pragma unroll
        for (int nt = 0; nt < 4; nt++)
#pragma unroll
            for (int i = 0; i < 4; i++) c[mt][nt][i] = 0.f;

    {
        float4 av[2], bv4;
#pragma unroll
        for (int i = 0; i < 2; i++) {
            int f4 = tid + i * 256;
            int m = f4 >> 2, kq = (f4 & 3) * 4;
            av[i] = *(const float4*)(A + (size_t)(m0 + m) * 1024 + kq);
        }
        int kr = tid >> 4, c4 = (tid & 15) * 4;
        bv4 = *(const float4*)(W + (size_t)kr * 1024 + n0 + c4);
        cvt_store_tile(Ah, Al, Bh, Bl, tid, av, bv4);
    }
    __syncthreads();

    int buf = 0;
    for (int kt = 0; kt < 1024; kt += 16) {
        float4 av[2], bv4;
        bool has_next = (kt + 16) < 1024;
        if (has_next) {
#pragma unroll
            for (int i = 0; i < 2; i++) {
                int f4 = tid + i * 256;
                int m = f4 >> 2, kq = (f4 & 3) * 4;
                av[i] = *(const float4*)(A + (size_t)(m0 + m) * 1024 + kt + 16 + kq);
            }
            int kr = tid >> 4, c4 = (tid & 15) * 4;
            bv4 = *(const float4*)(W + (size_t)(kt + 16 + kr) * 1024 + n0 + c4);
        }

        const float* ah = Ah + buf * AOFF;
        const float* al = Al + buf * AOFF;
        const float* bh = Bh + buf * BOFF;
        const float* bl = Bl + buf * BOFF;
#pragma unroll
        for (int k8 = 0; k8 < 16; k8 += 8) {
            unsigned a_[2][2][4], b_[4][2][2];
#pragma unroll
            for (int mt = 0; mt < 2; mt++) {
                int mb = wm * 32 + mt * 16;
                a_[mt][0][0] = __float_as_uint(ah[(k8 + tg) * 136 + mb + g]);
                a_[mt][0][1] = __float_as_uint(ah[(k8 + tg) * 136 + mb + g + 8]);
                a_[mt][0][2] = __float_as_uint(ah[(k8 + tg + 4) * 136 + mb + g]);
                a_[mt][0][3] = __float_as_uint(ah[(k8 + tg + 4) * 136 + mb + g + 8]);
                a_[mt][1][0] = __float_as_uint(al[(k8 + tg) * 136 + mb + g]);
                a_[mt][1][1] = __float_as_uint(al[(k8 + tg) * 136 + mb + g + 8]);
                a_[mt][1][2] = __float_as_uint(al[(k8 + tg + 4) * 136 + mb + g]);
                a_[mt][1][3] = __float_as_uint(al[(k8 + tg + 4) * 136 + mb + g + 8]);
            }
#pragma unroll
            for (int nt = 0; nt < 4; nt++) {
                int nb = wn * 32 + nt * 8;
                b_[nt][0][0] = __float_as_uint(bh[(k8 + tg) * 72 + nb + g]);
                b_[nt][0][1] = __float_as_uint(bh[(k8 + tg + 4) * 72 + nb + g]);
                b_[nt][1][0] = __float_as_uint(bl[(k8 + tg) * 72 + nb + g]);
                b_[nt][1][1] = __float_as_uint(bl[(k8 + tg + 4) * 72 + nb + g]);
            }
#pragma unroll
            for (int mt = 0; mt < 2; mt++)
#pragma unroll
                for (int nt = 0; nt < 4; nt++) {
                    mma_tf32(c[mt][nt], a_[mt][0], b_[nt][0]);
                    mma_tf32(c[mt][nt], a_[mt][0], b_[nt][1]);
                    mma_tf32(c[mt][nt], a_[mt][1], b_[nt][0]);
                }
        }

        if (has_next) {
            int nbuf = buf ^ 1;
            cvt_store_tile(Ah + nbuf * AOFF, Al + nbuf * AOFF,
                           Bh + nbuf * BOFF, Bl + nbuf * BOFF, tid, av, bv4);
            __syncthreads();
            buf = nbuf;
        }
    }

#pragma unroll
    for (int mt = 0; mt < 2; mt++)
#pragma unroll
        for (int nt = 0; nt < 4; nt++)
#pragma unroll
            for (int ci = 0; ci < 4; ci++) {
                int row = m0 + wm * 32 + mt * 16 + g + (ci >> 1) * 8;
                int col = n0 + wn * 32 + nt * 8 + tg * 2 + (ci & 1);
                float v = fmaxf(c[mt][nt][ci] + bias[col], 0.f);
                if (SCATTER) {
                    int b = row >> 10, s = row & 1023;
                    int h = col >> 6, d = col & 63;
                    out[(((size_t)(b * NH + h)) * SQ + s) * DKH + d] = v;
                } else {
                    out[(size_t)row * 1024 + col] = v;
                }
            }
}

__global__ void __launch_bounds__(256) qkv_gemm_kernel(
    const float* __restrict__ x,
    const float* __restrict__ Wq, const float* __restrict__ bq, float* __restrict__ oq,
    const float* __restrict__ Wk, const float* __restrict__ bk, float* __restrict__ ok,
    const float* __restrict__ Wv, const float* __restrict__ bv, float* __restrict__ ov)
{
    const float* W; const float* bias; float* out;
    if (blockIdx.z == 0)      { W = Wq; bias = bq; out = oq; }
    else if (blockIdx.z == 1) { W = Wk; bias = bk; out = ok; }
    else                      { W = Wv; bias = bv; out = ov; }
    gemm_body<1>(x, W, bias, out);
}

__global__ void __launch_bounds__(256) out_gemm_kernel(
    const float* __restrict__ A, const float* __restrict__ W,
    const float* __restrict__ bias, float* __restrict__ out)
{
    gemm_body<0>(A, W, bias, out);
}

// ---------------- V suffix sums ---------------------------------------------
__global__ void __launch_bounds__(1024) vsuf_kernel() {
    int bh = blockIdx.x;
    __shared__ float part[32][64];
    int d = threadIdx.x & 63;
    int jj = threadIdx.x >> 6;
#pragma unroll
    for (int p = 0; p < 2; p++) {
        int j = p * 16 + jj;
        const float* vp = g_v + ((size_t)bh * 1024 + j * 32) * 64 + d;
        float sum = 0.f;
#pragma unroll
        for (int s = 0; s < 32; s++) sum += vp[s * 64];
        part[j][d] = sum;
    }
    __syncthreads();
    if (threadIdx.x < 64) {
        float run = 0.f;
        for (int j = 31; j >= 0; j--) {
            run += part[j][threadIdx.x];
            g_vsuf[((size_t)bh * 32 + j) * 64 + threadIdx.x] = run;
        }
    }
}

// ---------------- fused attention: d-split lane pairs -----------------------
// 256 threads; warp w handles 16 q-rows; lanes l and l^16 co-own row (l&15).
// Each thread holds half the head-dim (32 floats) for q and o.
__global__ void __launch_bounds__(256) attn_kernel(
    const float* __restrict__ pos, const int* __restrict__ mask)
{
    int qb = blockIdx.x, h = blockIdx.y, b = blockIdx.z;
    int tid = threadIdx.x;
    int lane = tid & 31;
    int warp = tid >> 5;                 // 0..7
    int rowi = warp * 16 + (lane & 15);  // 0..127 row within block
    int half = lane >> 4;                // 0 or 1
    int db = half * 32;                  // d-range base
    int qrow = qb * 128 + rowi;

    __shared__ float ks[32][64];
    __shared__ float vs[32][64];
    __shared__ float ps[128][33];

    size_t bh = (size_t)(b * NH + h);
    const float* qp = g_q + (bh * SQ + qrow) * DKH + db;

    float q[32], o[32];
#pragma unroll
    for (int d = 0; d < 32; d += 4) {
        float4 t = *(const float4*)(qp + d);
        q[d] = t.x; q[d + 1] = t.y; q[d + 2] = t.z; q[d + 3] = t.w;
        o[d] = 0.f; o[d + 1] = 0.f; o[d + 2] = 0.f; o[d + 3] = 0.f;
    }
    float m = -INFINITY, l = 0.f;

    const float4* kbase = (const float4*)(g_k + bh * SQ * DKH);
    const float4* vbase = (const float4*)(g_v + bh * SQ * DKH);
    unsigned bernbase = (unsigned)(bh * SQ + qrow) * 32u;

    int kb_end = (qb + 1) * 128;

    for (int kb = 0; kb < kb_end; kb += 32) {
        __syncthreads();
        {
            const float4* kg4 = kbase + kb * 16;
            const float4* vg4 = vbase + kb * 16;
            float4* ksm = (float4*)&ks[0][0];
            float4* vsm = (float4*)&vs[0][0];
#pragma unroll
            for (int i = 0; i < 2; i++) {
                ksm[tid + i * 256] = kg4[tid + i * 256];
                vsm[tid + i * 256] = vg4[tid + i * 256];
            }
#pragma unroll
            for (int i = 0; i < 16; i++) {
                int idx = tid + i * 256;
                int r = idx >> 5, cc = idx & 31;
                ps[r][cc] = pos[((size_t)b * SQ + qb * 128 + r) * SQ + kb + cc];
            }
        }
        __syncthreads();

        // kb <= qrow is warp-uniform: a warp's 16 rows share floor(qrow/32)
        if (kb <= qrow) {
            unsigned bw = g_bern[bernbase + (kb >> 5)];
            unsigned mw = __ballot_sync(0xffffffffu,
                                        mask[b * SQ + kb + lane] != 0);
#pragma unroll
            for (int hf2 = 0; hf2 < 2; hf2++) {
                float s[16];
#pragma unroll
                for (int j = 0; j < 16; j++) {
                    int kk = hf2 * 16 + j;
                    float s0 = 0.f, s1 = 0.f, s2 = 0.f, s3 = 0.f;
#pragma unroll
                    for (int d = 0; d < 32; d += 16) {
                        float4 k0 = *(const float4*)&ks[kk][db + d];
                        float4 k1 = *(const float4*)&ks[kk][db + d + 4];
                        float4 k2 = *(const float4*)&ks[kk][db + d + 8];
                        float4 k3 = *(const float4*)&ks[kk][db + d + 12];
                        s0 = fmaf(q[d], k0.x, s0);      s0 = fmaf(q[d + 1], k0.y, s0);
                        s0 = fmaf(q[d + 2], k0.z, s0);  s0 = fmaf(q[d + 3], k0.w, s0);
                        s1 = fmaf(q[d + 4], k1.x, s1);  s1 = fmaf(q[d + 5], k1.y, s1);
                        s1 = fmaf(q[d + 6], k1.z, s1);  s1 = fmaf(q[d + 7], k1.w, s1);
                        s2 = fmaf(q[d + 8], k2.x, s2);  s2 = fmaf(q[d + 9], k2.y, s2);
                        s2 = fmaf(q[d + 10], k2.z, s2); s2 = fmaf(q[d + 11], k2.w, s2);
                        s3 = fmaf(q[d + 12], k3.x, s3); s3 = fmaf(q[d + 13], k3.y, s3);
                        s3 = fmaf(q[d + 14], k3.z, s3); s3 = fmaf(q[d + 15], k3.w, s3);
                    }
                    float sp = (s0 + s1) + (s2 + s3);
                    float sfull = sp + __shfl_xor_sync(0xffffffffu, sp, 16);
                    float val = sfull * 0.125f + ps[rowi][kk];
                    if ((bw >> kk) & 1u) val = val + (-1e9f);
                    int kg = kb + kk;
                    if (((mw >> kk) & 1u) | (unsigned)(kg > qrow)) val = -1e9f;
                    s[j] = val;
                }
                float vmax = s[0];
#pragma unroll
                for (int j = 1; j < 16; j++) vmax = fmaxf(vmax, s[j]);
                if (vmax > m) {
                    float corr = __expf(m - vmax);
                    l *= corr;
#pragma unroll
                    for (int d = 0; d < 32; d++) o[d] *= corr;
                    m = vmax;
                }
#pragma unroll
                for (int j = 0; j < 16; j++) {
                    float p = __expf(s[j] - m);
                    l += p;
                    int kk = hf2 * 16 + j;
#pragma unroll
                    for (int d = 0; d < 32; d += 4) {
                        float4 vv = *(const float4*)&vs[kk][db + d];
                        o[d]     = fmaf(p, vv.x, o[d]);
                        o[d + 1] = fmaf(p, vv.y, o[d + 1]);
                        o[d + 2] = fmaf(p, vv.z, o[d + 2]);
                        o[d + 3] = fmaf(p, vv.w, o[d + 3]);
                    }
                }
            }
        }
    }

    // causal tail: keys kg > qrow all have val == -1e9 exactly
    int jt = (qrow >> 5) + 1;
    if (jt < 32) {
        float pt = __expf(-1e9f - m);
        l += pt * (float)(1024 - jt * 32);
        if (pt > 0.f) {
            const float* sp = g_vsuf + ((size_t)(bh * 32 + jt)) * 64 + db;
#pragma unroll
            for (int d = 0; d < 32; d++) o[d] = fmaf(pt, sp[d], o[d]);
        }
    }

    float inv = 1.0f / l;
    float* op = g_ao + (((size_t)b * SQ + qrow) * NH + h) * DKH + db;
#pragma unroll
    for (int d = 0; d < 32; d += 4) {
        float4 t;
        t.x = o[d] * inv; t.y = o[d + 1] * inv;
        t.z = o[d + 2] * inv; t.w = o[d + 3] * inv;
        *(float4*)(op + d) = t;
    }
}

// ---------------- launch ----------------------------------------------------
extern "C" void kernel_launch(void* const* d_in, const int* in_sizes, int n_in,
                              void* d_out, int out_size) {
    (void)in_sizes; (void)n_in; (void)out_size;
    const float* x    = (const float*)d_in[0];
    const int*   mask = (const int*)d_in[1];
    const float* pos  = (const float*)d_in[2];
    const float* Wq = (const float*)d_in[4];
    const float* bq = (const float*)d_in[5];
    const float* Wk = (const float*)d_in[6];
    const float* bk = (const float*)d_in[7];
    const float* Wv = (const float*)d_in[8];
    const float* bv = (const float*)d_in[9];
    const float* Wo = (const float*)d_in[10];
    const float* bo = (const float*)d_in[11];
    float* out = (float*)d_out;

    float *pq, *pk, *pv, *pao;
    cudaGetSymbolAddress((void**)&pq,  g_q);
    cudaGetSymbolAddress((void**)&pk,  g_k);
    cudaGetSymbolAddress((void**)&pv,  g_v);
    cudaGetSymbolAddress((void**)&pao, g_ao);

    static int smem_set = 0;
    if (!smem_set) {
        cudaFuncSetAttribute(qkv_gemm_kernel,
            cudaFuncAttributeMaxDynamicSharedMemorySize, SMEM_GEMM_BYTES);
        cudaFuncSetAttribute(out_gemm_kernel,
            cudaFuncAttributeMaxDynamicSharedMemorySize, SMEM_GEMM_BYTES);
        smem_set = 1;
    }

    bern_kernel<<<NELEM / 256, 256>>>();

    dim3 gg(16, 32, 3);
    qkv_gemm_kernel<<<gg, 256, SMEM_GEMM_BYTES>>>(
        x, Wq, bq, pq, Wk, bk, pk, Wv, bv, pv);

    vsuf_kernel<<<64, 1024>>>();

    dim3 ga(8, NH, NB);
    attn_kernel<<<ga, 256>>>(pos, mask);

    dim3 go(16, 32, 1);
    out_gemm_kernel<<<go, 256, SMEM_GEMM_BYTES>>>(pao, Wo, bo, out);
}

// round 6
// speedup vs baseline: 1.4718x; 1.1384x over previous
#include <cuda_runtime.h>
#include <math.h>

#define NB 4
#define SQ 1024
#define DM 1024
#define NH 16
#define DKH 64
#define NKV (NB * NH * SQ * DKH)
#define NELEM 67108864u

// ---------------- scratch ----------------------------------------------------
__device__ float g_q[NKV];            // [b,h,s,d]
__device__ float g_k[NKV];
__device__ float g_v[NKV];
__device__ float g_ao[NB * SQ * NH * DKH];        // [b,q,h,d]
__device__ unsigned g_bern[NELEM / 32];
__device__ float g_vsuf[64 * 32 * 64];

// ---------------- threefry2x32 (JAX partitionable, key=(0,42)) --------------
__device__ __forceinline__ unsigned rotl32(unsigned x, int r) {
    return __funnelshift_l(x, x, r);
}

__global__ void __launch_bounds__(256) bern_kernel() {
    unsigned e = blockIdx.x * 256u + threadIdx.x;
    unsigned qr = (e >> 10) & 1023u;
    unsigned kg0 = e & 992u;
    if (kg0 > qr) return;             // dead bits (causal overwrite), warp-uniform

    unsigned x0 = 0u;
    unsigned x1 = e;
    const unsigned ks1 = 42u;
    const unsigned ks2 = 0x1BD11BDAu ^ 42u;
    x1 += ks1;
#define TF_RND(r) { x0 += x1; x1 = rotl32(x1, (r)); x1 ^= x0; }
    TF_RND(13) TF_RND(15) TF_RND(26) TF_RND(6)
    x0 += ks1; x1 += ks2 + 1u;
    TF_RND(17) TF_RND(29) TF_RND(16) TF_RND(24)
    x0 += ks2; x1 += 0u + 2u;
    TF_RND(13) TF_RND(15) TF_RND(26) TF_RND(6)
    x0 += 0u; x1 += ks1 + 3u;
    TF_RND(17) TF_RND(29) TF_RND(16) TF_RND(24)
    x0 += ks1; x1 += ks2 + 4u;
    TF_RND(13) TF_RND(15) TF_RND(26) TF_RND(6)
    x0 += ks2; x1 += 0u + 5u;
#undef TF_RND
    unsigned bits = x0 ^ x1;
    unsigned keep = ((bits >> 9) < 2516583u) ? 1u : 0u;    // uniform < 0.3f
    unsigned w = __ballot_sync(0xffffffffu, keep != 0u);
    if ((threadIdx.x & 31u) == 0u) g_bern[e >> 5] = w;
}

// ---------------- tf32 helpers ----------------------------------------------
__device__ __forceinline__ unsigned f2tf(float x) {
    unsigned r;
    asm("cvt.rna.tf32.f32 %0, %1;" : "=r"(r) : "f"(x));
    return r;
}

__device__ __forceinline__ void mma_tf32(float c[4], const unsigned a[4], const unsigned b[2]) {
    asm volatile(
        "mma.sync.aligned.m16n8k8.row.col.f32.tf32.tf32.f32 "
        "{%0,%1,%2,%3}, {%4,%5,%6,%7}, {%8,%9}, {%0,%1,%2,%3};"
        : "+f"(c[0]), "+f"(c[1]), "+f"(c[2]), "+f"(c[3])
        : "r"(a[0]), "r"(a[1]), "r"(a[2]), "r"(a[3]), "r"(b[0]), "r"(b[1]));
}

// ---------------- tf32x3 double-buffered GEMM + bias + relu -----------------
#define AOFF 2176
#define BOFF 1152
#define SMEM_GEMM_BYTES ((2 * AOFF * 2 + 2 * BOFF * 2) * 4)   // 53248

__device__ __forceinline__ void cvt_store_tile(
    float* Ahb, float* Alb, float* Bhb, float* Blb,
    int tid, const float4* av, float4 bv4)
{
#pragma unroll
    for (int i = 0; i < 2; i++) {
        int f4 = tid + i * 256;
        int m = f4 >> 2, kq = (f4 & 3) * 4;
        float vv[4] = {av[i].x, av[i].y, av[i].z, av[i].w};
#pragma unroll
        for (int j = 0; j < 4; j++) {
            float hf = __uint_as_float(f2tf(vv[j]));
            Ahb[(kq + j) * 136 + m] = hf;
            Alb[(kq + j) * 136 + m] = __uint_as_float(f2tf(vv[j] - hf));
        }
    }
    {
        int kr = tid >> 4, c4 = (tid & 15) * 4;
        float vv[4] = {bv4.x, bv4.y, bv4.z, bv4.w};
#pragma unroll
        for (int j = 0; j < 4; j++) {
            float hf = __uint_as_float(f2tf(vv[j]));
            Bhb[kr * 72 + c4 + j] = hf;
            Blb[kr * 72 + c4 + j] = __uint_as_float(f2tf(vv[j] - hf));
        }
    }
}

template <int SCATTER>
__device__ __forceinline__ void gemm_body(
    const float* __restrict__ A, const float* __restrict__ W,
    const float* __restrict__ bias, float* __restrict__ out)
{
    extern __shared__ float sm[];
    float* Ah = sm;
    float* Al = sm + 2 * AOFF;
    float* Bh = sm + 4 * AOFF;
    float* Bl = sm + 4 * AOFF + 2 * BOFF;

    int tid = threadIdx.x;
    int lane = tid & 31, warp = tid >> 5;
    int wm = warp & 3, wn = warp >> 2;
    int g = lane >> 2, tg = lane & 3;
    int m0 = blockIdx.y * 128, n0 = blockIdx.x * 64;

    float c[2][4][4];
#pragma unroll
    for (int mt = 0; mt < 2; mt++)
#pragma unroll
        for (int nt = 0; nt < 4; nt++)
#pragma unroll
            for (int i = 0; i < 4; i++) c[mt][nt][i] = 0.f;

    {
        float4 av[2], bv4;
#pragma unroll
        for (int i = 0; i < 2; i++) {
            int f4 = tid + i * 256;
            int m = f4 >> 2, kq = (f4 & 3) * 4;
            av[i] = *(const float4*)(A + (size_t)(m0 + m) * 1024 + kq);
        }
        int kr = tid >> 4, c4 = (tid & 15) * 4;
        bv4 = *(const float4*)(W + (size_t)kr * 1024 + n0 + c4);
        cvt_store_tile(Ah, Al, Bh, Bl, tid, av, bv4);
    }
    __syncthreads();

    int buf = 0;
    for (int kt = 0; kt < 1024; kt += 16) {
        float4 av[2], bv4;
        bool has_next = (kt + 16) < 1024;
        if (has_next) {
#pragma unroll
            for (int i = 0; i < 2; i++) {
                int f4 = tid + i * 256;
                int m = f4 >> 2, kq = (f4 & 3) * 4;
                av[i] = *(const float4*)(A + (size_t)(m0 + m) * 1024 + kt + 16 + kq);
            }
            int kr = tid >> 4, c4 = (tid & 15) * 4;
            bv4 = *(const float4*)(W + (size_t)(kt + 16 + kr) * 1024 + n0 + c4);
        }

        const float* ah = Ah + buf * AOFF;
        const float* al = Al + buf * AOFF;
        const float* bh = Bh + buf * BOFF;
        const float* bl = Bl + buf * BOFF;
#pragma unroll
        for (int k8 = 0; k8 < 16; k8 += 8) {
            unsigned a_[2][2][4], b_[4][2][2];
#pragma unroll
            for (int mt = 0; mt < 2; mt++) {
                int mb = wm * 32 + mt * 16;
                a_[mt][0][0] = __float_as_uint(ah[(k8 + tg) * 136 + mb + g]);
                a_[mt][0][1] = __float_as_uint(ah[(k8 + tg) * 136 + mb + g + 8]);
                a_[mt][0][2] = __float_as_uint(ah[(k8 + tg + 4) * 136 + mb + g]);
                a_[mt][0][3] = __float_as_uint(ah[(k8 + tg + 4) * 136 + mb + g + 8]);
                a_[mt][1][0] = __float_as_uint(al[(k8 + tg) * 136 + mb + g]);
                a_[mt][1][1] = __float_as_uint(al[(k8 + tg) * 136 + mb + g + 8]);
                a_[mt][1][2] = __float_as_uint(al[(k8 + tg + 4) * 136 + mb + g]);
                a_[mt][1][3] = __float_as_uint(al[(k8 + tg + 4) * 136 + mb + g + 8]);
            }
#pragma unroll
            for (int nt = 0; nt < 4; nt++) {
                int nb = wn * 32 + nt * 8;
                b_[nt][0][0] = __float_as_uint(bh[(k8 + tg) * 72 + nb + g]);
                b_[nt][0][1] = __float_as_uint(bh[(k8 + tg + 4) * 72 + nb + g]);
                b_[nt][1][0] = __float_as_uint(bl[(k8 + tg) * 72 + nb + g]);
                b_[nt][1][1] = __float_as_uint(bl[(k8 + tg + 4) * 72 + nb + g]);
            }
#pragma unroll
            for (int mt = 0; mt < 2; mt++)
#pragma unroll
                for (int nt = 0; nt < 4; nt++) {
                    mma_tf32(c[mt][nt], a_[mt][0], b_[nt][0]);
                    mma_tf32(c[mt][nt], a_[mt][0], b_[nt][1]);
                    mma_tf32(c[mt][nt], a_[mt][1], b_[nt][0]);
                }
        }

        if (has_next) {
            int nbuf = buf ^ 1;
            cvt_store_tile(Ah + nbuf * AOFF, Al + nbuf * AOFF,
                           Bh + nbuf * BOFF, Bl + nbuf * BOFF, tid, av, bv4);
            __syncthreads();
            buf = nbuf;
        }
    }

#pragma unroll
    for (int mt = 0; mt < 2; mt++)
#pragma unroll
        for (int nt = 0; nt < 4; nt++)
#pragma unroll
            for (int ci = 0; ci < 4; ci++) {
                int row = m0 + wm * 32 + mt * 16 + g + (ci >> 1) * 8;
                int col = n0 + wn * 32 + nt * 8 + tg * 2 + (ci & 1);
                float v = fmaxf(c[mt][nt][ci] + bias[col], 0.f);
                if (SCATTER) {
                    int b = row >> 10, s = row & 1023;
                    int h = col >> 6, d = col & 63;
                    out[(((size_t)(b * NH + h)) * SQ + s) * DKH + d] = v;
                } else {
                    out[(size_t)row * 1024 + col] = v;
                }
            }
}

__global__ void __launch_bounds__(256) qkv_gemm_kernel(
    const float* __restrict__ x,
    const float* __restrict__ Wq, const float* __restrict__ bq, float* __restrict__ oq,
    const float* __restrict__ Wk, const float* __restrict__ bk, float* __restrict__ ok,
    const float* __restrict__ Wv, const float* __restrict__ bv, float* __restrict__ ov)
{
    const float* W; const float* bias; float* out;
    if (blockIdx.z == 0)      { W = Wq; bias = bq; out = oq; }
    else if (blockIdx.z == 1) { W = Wk; bias = bk; out = ok; }
    else                      { W = Wv; bias = bv; out = ov; }
    gemm_body<1>(x, W, bias, out);
}

__global__ void __launch_bounds__(256) out_gemm_kernel(
    const float* __restrict__ A, const float* __restrict__ W,
    const float* __restrict__ bias, float* __restrict__ out)
{
    gemm_body<0>(A, W, bias, out);
}

// ---------------- V suffix sums ---------------------------------------------
__global__ void __launch_bounds__(1024) vsuf_kernel() {
    int bh = blockIdx.x;
    __shared__ float part[32][64];
    int d = threadIdx.x & 63;
    int jj = threadIdx.x >> 6;
#pragma unroll
    for (int p = 0; p < 2; p++) {
        int j = p * 16 + jj;
        const float* vp = g_v + ((size_t)bh * 1024 + j * 32) * 64 + d;
        float sum = 0.f;
#pragma unroll
        for (int s = 0; s < 32; s++) sum += vp[s * 64];
        part[j][d] = sum;
    }
    __syncthreads();
    if (threadIdx.x < 64) {
        float run = 0.f;
        for (int j = 31; j >= 0; j--) {
            run += part[j][threadIdx.x];
            g_vsuf[((size_t)bh * 32 + j) * 64 + threadIdx.x] = run;
        }
    }
}

// ---------------- MMA flash attention ----------------------------------------
// 256 threads = 8 warps; warp w owns q-rows [qb*128+w*16, +16).
// Per 32-key tile: S = Q@K^T (tf32x3 m16n8k8), softmax in C-frag layout,
// P via smem -> A-frags, O += P@V (tf32x3).
#define KS_W 76   // K smem row stride (keys-major [32][76]) : banks (12g+tg) distinct
#define VS_W 72   // V smem row stride [32][72] : banks (8tg+g) distinct
#define PS_W 33   // pos tile stride
#define PT_W 36   // P tile stride : banks (4g+tg) distinct
#define SMEM_ATTN_FLOATS (2*32*KS_W + 2*32*VS_W + 128*PS_W + 8*16*PT_W)
#define SMEM_ATTN_BYTES (SMEM_ATTN_FLOATS * 4)

__global__ void __launch_bounds__(256) attn_kernel(
    const float* __restrict__ pos, const int* __restrict__ mask)
{
    extern __shared__ float sm[];
    float* Ks_hi = sm;                          // [32][KS_W]
    float* Ks_lo = Ks_hi + 32 * KS_W;
    float* Vs_hi = Ks_lo + 32 * KS_W;           // [32][VS_W]
    float* Vs_lo = Vs_hi + 32 * VS_W;
    float* ps    = Vs_lo + 32 * VS_W;           // [128][PS_W]
    float* PtAll = ps + 128 * PS_W;             // 8 x [16][PT_W]

    int qb = blockIdx.x, h = blockIdx.y, b = blockIdx.z;
    int tid = threadIdx.x;
    int lane = tid & 31, warp = tid >> 5;
    int g = lane >> 2, tg = lane & 3;
    float* Pt = PtAll + warp * 16 * PT_W;

    int qr0 = qb * 128 + warp * 16;             // warp's first global q-row
    int qrow_g = qr0 + g;
    int qrow_h = qr0 + g + 8;
    size_t bh = (size_t)(b * NH + h);

    // Q fragments (register-resident, hi/lo)
    unsigned qa_hi[8][4], qa_lo[8][4];
    {
        const float* qbase = g_q + (bh * SQ + qr0) * DKH;
#pragma unroll
        for (int ks = 0; ks < 8; ks++) {
            float v0 = qbase[g * 64 + ks * 8 + tg];
            float v1 = qbase[(g + 8) * 64 + ks * 8 + tg];
            float v2 = qbase[g * 64 + ks * 8 + tg + 4];
            float v3 = qbase[(g + 8) * 64 + ks * 8 + tg + 4];
            qa_hi[ks][0] = f2tf(v0); qa_lo[ks][0] = f2tf(v0 - __uint_as_float(qa_hi[ks][0]));
            qa_hi[ks][1] = f2tf(v1); qa_lo[ks][1] = f2tf(v1 - __uint_as_float(qa_hi[ks][1]));
            qa_hi[ks][2] = f2tf(v2); qa_lo[ks][2] = f2tf(v2 - __uint_as_float(qa_hi[ks][2]));
            qa_hi[ks][3] = f2tf(v3); qa_lo[ks][3] = f2tf(v3 - __uint_as_float(qa_hi[ks][3]));
        }
    }

    float o[8][4];
#pragma unroll
    for (int nt = 0; nt < 8; nt++)
#pragma unroll
        for (int i = 0; i < 4; i++) o[nt][i] = 0.f;
    float m_g = -INFINITY, m_h = -INFINITY, l_g = 0.f, l_h = 0.f;

    int kb_end = (qb + 1) * 128;
    // cooperative K/V load mapping: thread -> (d, key-group)
    int ld_d = tid & 63;
    int ld_kg = tid >> 6;       // 0..3 (8 keys each)

    for (int kb = 0; kb < kb_end; kb += 32) {
        __syncthreads();
        // K/V tile -> smem hi/lo
        {
            const float* kgp = g_k + (bh * SQ + kb) * DKH;
            const float* vgp = g_v + (bh * SQ + kb) * DKH;
#pragma unroll
            for (int ki = 0; ki < 8; ki++) {
                int key = ld_kg * 8 + ki;
                float kv = kgp[key * 64 + ld_d];
                float vv = vgp[key * 64 + ld_d];
                unsigned khi = f2tf(kv);
                unsigned vhi = f2tf(vv);
                Ks_hi[key * KS_W + ld_d] = __uint_as_float(khi);
                Ks_lo[key * KS_W + ld_d] = __uint_as_float(f2tf(kv - __uint_as_float(khi)));
                Vs_hi[key * VS_W + ld_d] = __uint_as_float(vhi);
                Vs_lo[key * VS_W + ld_d] = __uint_as_float(f2tf(vv - __uint_as_float(vhi)));
            }
            // pos tile 128x32
#pragma unroll
            for (int i = 0; i < 16; i++) {
                int idx = tid + i * 256;
                int r = idx >> 5, cc = idx & 31;
                ps[r * PS_W + cc] = pos[((size_t)b * SQ + qb * 128 + r) * SQ + kb + cc];
            }
        }
        __syncthreads();

        if (kb <= qr0) {        // warp-uniform (all 16 rows share qrow>>5)
            // ---- S = Q @ K^T ----
            float sc[4][4];
#pragma unroll
            for (int nt = 0; nt < 4; nt++)
#pragma unroll
                for (int i = 0; i < 4; i++) sc[nt][i] = 0.f;
#pragma unroll
            for (int ks = 0; ks < 8; ks++) {
#pragma unroll
                for (int nt = 0; nt < 4; nt++) {
                    unsigned bhh[2], bll[2];
                    bhh[0] = __float_as_uint(Ks_hi[(nt * 8 + g) * KS_W + ks * 8 + tg]);
                    bhh[1] = __float_as_uint(Ks_hi[(nt * 8 + g) * KS_W + ks * 8 + tg + 4]);
                    bll[0] = __float_as_uint(Ks_lo[(nt * 8 + g) * KS_W + ks * 8 + tg]);
                    bll[1] = __float_as_uint(Ks_lo[(nt * 8 + g) * KS_W + ks * 8 + tg + 4]);
                    mma_tf32(sc[nt], qa_hi[ks], bhh);
                    mma_tf32(sc[nt], qa_hi[ks], bll);
                    mma_tf32(sc[nt], qa_lo[ks], bhh);
                }
            }

            // ---- masks / bias ----
            unsigned bw_g = g_bern[(bh * SQ + qrow_g) * 32u + (kb >> 5)];
            unsigned bw_h = g_bern[(bh * SQ + qrow_h) * 32u + (kb >> 5)];
            unsigned mw = __ballot_sync(0xffffffffu, mask[b * SQ + kb + lane] != 0);

            float vals[4][4];
#pragma unroll
            for (int nt = 0; nt < 4; nt++) {
                int c0 = nt * 8 + tg * 2, c1 = c0 + 1;
                float v00 = sc[nt][0] * 0.125f + ps[(warp * 16 + g) * PS_W + c0];
                float v01 = sc[nt][1] * 0.125f + ps[(warp * 16 + g) * PS_W + c1];
                float v10 = sc[nt][2] * 0.125f + ps[(warp * 16 + g + 8) * PS_W + c0];
                float v11 = sc[nt][3] * 0.125f + ps[(warp * 16 + g + 8) * PS_W + c1];
                if ((bw_g >> c0) & 1u) v00 += -1e9f;
                if ((bw_g >> c1) & 1u) v01 += -1e9f;
                if ((bw_h >> c0) & 1u) v10 += -1e9f;
                if ((bw_h >> c1) & 1u) v11 += -1e9f;
                int kg0 = kb + c0, kg1 = kb + c1;
                if (((mw >> c0) & 1u) | (unsigned)(kg0 > qrow_g)) v00 = -1e9f;
                if (((mw >> c1) & 1u) | (unsigned)(kg1 > qrow_g)) v01 = -1e9f;
                if (((mw >> c0) & 1u) | (unsigned)(kg0 > qrow_h)) v10 = -1e9f;
                if (((mw >> c1) & 1u) | (unsigned)(kg1 > qrow_h)) v11 = -1e9f;
                vals[nt][0] = v00; vals[nt][1] = v01;
                vals[nt][2] = v10; vals[nt][3] = v11;
            }

            // ---- online softmax (rows g and g+8) ----
            float rmax_g = vals[0][0], rmax_h = vals[0][2];
#pragma unroll
            for (int nt = 0; nt < 4; nt++) {
                rmax_g = fmaxf(rmax_g, fmaxf(vals[nt][0], vals[nt][1]));
                rmax_h = fmaxf(rmax_h, fmaxf(vals[nt][2], vals[nt][3]));
            }
            rmax_g = fmaxf(rmax_g, __shfl_xor_sync(0xffffffffu, rmax_g, 1));
            rmax_g = fmaxf(rmax_g, __shfl_xor_sync(0xffffffffu, rmax_g, 2));
            rmax_h = fmaxf(rmax_h, __shfl_xor_sync(0xffffffffu, rmax_h, 1));
            rmax_h = fmaxf(rmax_h, __shfl_xor_sync(0xffffffffu, rmax_h, 2));

            float mn_g = fmaxf(m_g, rmax_g);
            float mn_h = fmaxf(m_h, rmax_h);
            float corr_g = __expf(m_g - mn_g);
            float corr_h = __expf(m_h - mn_h);
            m_g = mn_g; m_h = mn_h;
            l_g *= corr_g; l_h *= corr_h;
#pragma unroll
            for (int nt = 0; nt < 8; nt++) {
                o[nt][0] *= corr_g; o[nt][1] *= corr_g;
                o[nt][2] *= corr_h; o[nt][3] *= corr_h;
            }

            float psum_g = 0.f, psum_h = 0.f;
#pragma unroll
            for (int nt = 0; nt < 4; nt++) {
                int c0 = nt * 8 + tg * 2;
                float p00 = __expf(vals[nt][0] - m_g);
                float p01 = __expf(vals[nt][1] - m_g);
                float p10 = __expf(vals[nt][2] - m_h);
                float p11 = __expf(vals[nt][3] - m_h);
                psum_g += p00 + p01;
                psum_h += p10 + p11;
                *(float2*)&Pt[g * PT_W + c0] = make_float2(p00, p01);
                *(float2*)&Pt[(g + 8) * PT_W + c0] = make_float2(p10, p11);
            }
            psum_g += __shfl_xor_sync(0xffffffffu, psum_g, 1);
            psum_g += __shfl_xor_sync(0xffffffffu, psum_g, 2);
            psum_h += __shfl_xor_sync(0xffffffffu, psum_h, 1);
            psum_h += __shfl_xor_sync(0xffffffffu, psum_h, 2);
            l_g += psum_g; l_h += psum_h;

            __syncwarp();

            // ---- O += P @ V ----
#pragma unroll
            for (int ks = 0; ks < 4; ks++) {
                float p0 = Pt[g * PT_W + ks * 8 + tg];
                float p1 = Pt[(g + 8) * PT_W + ks * 8 + tg];
                float p2 = Pt[g * PT_W + ks * 8 + tg + 4];
                float p3 = Pt[(g + 8) * PT_W + ks * 8 + tg + 4];
                unsigned pa_hi[4], pa_lo[4];
                pa_hi[0] = f2tf(p0); pa_lo[0] = f2tf(p0 - __uint_as_float(pa_hi[0]));
                pa_hi[1] = f2tf(p1); pa_lo[1] = f2tf(p1 - __uint_as_float(pa_hi[1]));
                pa_hi[2] = f2tf(p2); pa_lo[2] = f2tf(p2 - __uint_as_float(pa_hi[2]));
                pa_hi[3] = f2tf(p3); pa_lo[3] = f2tf(p3 - __uint_as_float(pa_hi[3]));
#pragma unroll
                for (int nt = 0; nt < 8; nt++) {
                    unsigned bhh[2], bll[2];
                    bhh[0] = __float_as_uint(Vs_hi[(ks * 8 + tg) * VS_W + nt * 8 + g]);
                    bhh[1] = __float_as_uint(Vs_hi[(ks * 8 + tg + 4) * VS_W + nt * 8 + g]);
                    bll[0] = __float_as_uint(Vs_lo[(ks * 8 + tg) * VS_W + nt * 8 + g]);
                    bll[1] = __float_as_uint(Vs_lo[(ks * 8 + tg + 4) * VS_W + nt * 8 + g]);
                    mma_tf32(o[nt], pa_hi, bhh);
                    mma_tf32(o[nt], pa_hi, bll);
                    mma_tf32(o[nt], pa_lo, bhh);
                }
            }
            __syncwarp();
        }
    }

    // ---- causal tail (keys beyond last processed tile all have val==-1e9) ----
    int jt = (qrow_g >> 5) + 1;       // warp-uniform
    if (jt < 32) {
        float pt_g = __expf(-1e9f - m_g);
        float pt_h = __expf(-1e9f - m_h);
        l_g += pt_g * (float)(1024 - jt * 32);
        l_h += pt_h * (float)(1024 - jt * 32);
        const float* sp = g_vsuf + (bh * 32 + jt) * 64;
#pragma unroll
        for (int nt = 0; nt < 8; nt++) {
            int c0 = nt * 8 + tg * 2;
            float s0 = sp[c0], s1 = sp[c0 + 1];
            o[nt][0] = fmaf(pt_g, s0, o[nt][0]);
            o[nt][1] = fmaf(pt_g, s1, o[nt][1]);
            o[nt][2] = fmaf(pt_h, s0, o[nt][2]);
            o[nt][3] = fmaf(pt_h, s1, o[nt][3]);
        }
    }

    // ---- epilogue ----
    float ig = 1.0f / l_g, ih = 1.0f / l_h;
    float* og = g_ao + (((size_t)b * SQ + qrow_g) * NH + h) * DKH;
    float* oh = g_ao + (((size_t)b * SQ + qrow_h) * NH + h) * DKH;
#pragma unroll
    for (int nt = 0; nt < 8; nt++) {
        int c0 = nt * 8 + tg * 2;
        *(float2*)(og + c0) = make_float2(o[nt][0] * ig, o[nt][1] * ig);
        *(float2*)(oh + c0) = make_float2(o[nt][2] * ih, o[nt][3] * ih);
    }
}

// ---------------- launch ----------------------------------------------------
extern "C" void kernel_launch(void* const* d_in, const int* in_sizes, int n_in,
                              void* d_out, int out_size) {
    (void)in_sizes; (void)n_in; (void)out_size;
    const float* x    = (const float*)d_in[0];
    const int*   mask = (const int*)d_in[1];
    const float* pos  = (const float*)d_in[2];
    const float* Wq = (const float*)d_in[4];
    const float* bq = (const float*)d_in[5];
    const float* Wk = (const float*)d_in[6];
    const float* bk = (const float*)d_in[7];
    const float* Wv = (const float*)d_in[8];
    const float* bv = (const float*)d_in[9];
    const float* Wo = (const float*)d_in[10];
    const float* bo = (const float*)d_in[11];
    float* out = (float*)d_out;

    float *pq, *pk, *pv, *pao;
    cudaGetSymbolAddress((void**)&pq,  g_q);
    cudaGetSymbolAddress((void**)&pk,  g_k);
    cudaGetSymbolAddress((void**)&pv,  g_v);
    cudaGetSymbolAddress((void**)&pao, g_ao);

    static int smem_set = 0;
    if (!smem_set) {
        cudaFuncSetAttribute(qkv_gemm_kernel,
            cudaFuncAttributeMaxDynamicSharedMemorySize, SMEM_GEMM_BYTES);
        cudaFuncSetAttribute(out_gemm_kernel,
            cudaFuncAttributeMaxDynamicSharedMemorySize, SMEM_GEMM_BYTES);
        cudaFuncSetAttribute(attn_kernel,
            cudaFuncAttributeMaxDynamicSharedMemorySize, SMEM_ATTN_BYTES);
        smem_set = 1;
    }

    bern_kernel<<<NELEM / 256, 256>>>();

    dim3 gg(16, 32, 3);
    qkv_gemm_kernel<<<gg, 256, SMEM_GEMM_BYTES>>>(
        x, Wq, bq, pq, Wk, bk, pk, Wv, bv, pv);

    vsuf_kernel<<<64, 1024>>>();

    dim3 ga(8, NH, NB);
    attn_kernel<<<ga, 256, SMEM_ATTN_BYTES>>>(pos, mask);

    dim3 go(16, 32, 1);
    out_gemm_kernel<<<go, 256, SMEM_GEMM_BYTES>>>(pao, Wo, bo, out);
}

// round 7
// speedup vs baseline: 1.5896x; 1.0800x over previous
#include <cuda_runtime.h>
#include <math.h>

#define NB 4
#define SQ 1024
#define DM 1024
#define NH 16
#define DKH 64
#define NKV (NB * NH * SQ * DKH)
#define NELEM 67108864u

// ---------------- scratch ----------------------------------------------------
__device__ float g_q[NKV];            // [b,h,s,d]
__device__ float g_k[NKV];
__device__ float g_v[NKV];
__device__ float g_ao[NB * SQ * NH * DKH];        // [b,q,h,d]
__device__ unsigned g_bern[NELEM / 32];
__device__ float g_vsuf[64 * 32 * 64];

// ---------------- threefry2x32 (JAX partitionable, key=(0,42)) --------------
__device__ __forceinline__ unsigned rotl32(unsigned x, int r) {
    return __funnelshift_l(x, x, r);
}

// one element e -> bernoulli bit, ballot-packed by caller
__device__ __forceinline__ unsigned bern_bit(unsigned e) {
    unsigned x0 = 0u;
    unsigned x1 = e;
    const unsigned ks1 = 42u;
    const unsigned ks2 = 0x1BD11BDAu ^ 42u;
    x1 += ks1;
#define TF_RND(r) { x0 += x1; x1 = rotl32(x1, (r)); x1 ^= x0; }
    TF_RND(13) TF_RND(15) TF_RND(26) TF_RND(6)
    x0 += ks1; x1 += ks2 + 1u;
    TF_RND(17) TF_RND(29) TF_RND(16) TF_RND(24)
    x0 += ks2; x1 += 0u + 2u;
    TF_RND(13) TF_RND(15) TF_RND(26) TF_RND(6)
    x0 += 0u; x1 += ks1 + 3u;
    TF_RND(17) TF_RND(29) TF_RND(16) TF_RND(24)
    x0 += ks1; x1 += ks2 + 4u;
    TF_RND(13) TF_RND(15) TF_RND(26) TF_RND(6)
    x0 += ks2; x1 += 0u + 5u;
#undef TF_RND
    unsigned bits = x0 ^ x1;
    return ((bits >> 9) < 2516583u) ? 1u : 0u;   // uniform(bits) < 0.3f
}

// bern slice run inside the qkv kernel (blockIdx.z == 3): 256 blocks x 256 thr,
// each thread handles 1024 elements strided by 65536 (keeps ballot groups
// aligned and the causal dead-bit skip warp-uniform).
__device__ void bern_chunk(int blk, int tid) {
    unsigned t = (unsigned)blk * 256u + (unsigned)tid;
    for (unsigned i = 0; i < 1024u; i++) {
        unsigned e = t + i * 65536u;
        unsigned qr = (e >> 10) & 1023u;
        unsigned kg0 = e & 992u;
        if (kg0 > qr) continue;           // dead bits (causal overwrite), warp-uniform
        unsigned keep = bern_bit(e);
        unsigned w = __ballot_sync(0xffffffffu, keep != 0u);
        if ((tid & 31) == 0) g_bern[e >> 5] = w;
    }
}

// ---------------- tf32 helpers ----------------------------------------------
__device__ __forceinline__ unsigned f2tf(float x) {
    unsigned r;
    asm("cvt.rna.tf32.f32 %0, %1;" : "=r"(r) : "f"(x));
    return r;
}

__device__ __forceinline__ void mma_tf32(float c[4], const unsigned a[4], const unsigned b[2]) {
    asm volatile(
        "mma.sync.aligned.m16n8k8.row.col.f32.tf32.tf32.f32 "
        "{%0,%1,%2,%3}, {%4,%5,%6,%7}, {%8,%9}, {%0,%1,%2,%3};"
        : "+f"(c[0]), "+f"(c[1]), "+f"(c[2]), "+f"(c[3])
        : "r"(a[0]), "r"(a[1]), "r"(a[2]), "r"(a[3]), "r"(b[0]), "r"(b[1]));
}

__device__ __forceinline__ void cp16(float* dst_smem, const float* src) {
    unsigned d = (unsigned)__cvta_generic_to_shared(dst_smem);
    asm volatile("cp.async.cg.shared.global [%0], [%1], 16;" :: "r"(d), "l"(src) : "memory");
}

// ---------------- tf32x3 cp.async GEMM + bias + relu -------------------------
// C[4096,1024] = relu(A @ W + bias). BM=128, BN=128, BK=16, 3-stage pipeline.
// 8 warps as 4(M) x 2(N); warp tile 32x64 (mt=2, nt=8). Raw fp32 in smem;
// tf32 hi/lo split at fragment-load time.
#define AS_W 20                       // A row stride (floats): banks 20g+tg distinct, 80B%16==0
#define BS_W 136                      // B row stride: banks 8tg+g distinct, 544B%16==0
#define A_STAGE (128 * AS_W)          // 2560 floats
#define B_STAGE (16 * BS_W)           // 2176 floats
#define STAGE_FLOATS (A_STAGE + B_STAGE)
#define NSTAGE 3
#define SMEM_GEMM_BYTES (STAGE_FLOATS * NSTAGE * 4)   // 56832

__device__ __forceinline__ void issue_stage(
    const float* __restrict__ A, const float* __restrict__ W,
    int m0, int n0, int kt, float* stage, int tid)
{
    float* As = stage;
    float* Bs = stage + A_STAGE;
#pragma unroll
    for (int i = 0; i < 2; i++) {
        int c = tid + i * 256;
        int m = c >> 2, kq = c & 3;
        cp16(As + m * AS_W + kq * 4, A + (size_t)(m0 + m) * 1024 + kt + kq * 4);
    }
#pragma unroll
    for (int i = 0; i < 2; i++) {
        int c = tid + i * 256;
        int kr = c >> 5, nc = c & 31;
        cp16(Bs + kr * BS_W + nc * 4, W + (size_t)(kt + kr) * 1024 + n0 + nc * 4);
    }
    asm volatile("cp.async.commit_group;" ::: "memory");
}

template <int SCATTER>
__device__ __forceinline__ void gemm_body(
    const float* __restrict__ A, const float* __restrict__ W,
    const float* __restrict__ bias, float* __restrict__ out)
{
    extern __shared__ float sm[];
    int tid = threadIdx.x;
    int lane = tid & 31, warp = tid >> 5;
    int wm = warp & 3, wn = warp >> 2;       // 4 x 2 warps
    int g = lane >> 2, tg = lane & 3;
    int m0 = blockIdx.y * 128, n0 = blockIdx.x * 128;

    float c[2][8][4];
#pragma unroll
    for (int mt = 0; mt < 2; mt++)
#pragma unroll
        for (int nt = 0; nt < 8; nt++)
#pragma unroll
            for (int i = 0; i < 4; i++) c[mt][nt][i] = 0.f;

    issue_stage(A, W, m0, n0, 0, sm, tid);
    issue_stage(A, W, m0, n0, 16, sm + STAGE_FLOATS, tid);

    int buf = 0;
    for (int it = 0; it < 64; it++) {
        if (it < 62) { asm volatile("cp.async.wait_group 1;" ::: "memory"); }
        else         { asm volatile("cp.async.wait_group 0;" ::: "memory"); }
        __syncthreads();

        if (it + 2 < 64) {
            int nbuf = buf + 2; if (nbuf >= NSTAGE) nbuf -= NSTAGE;
            issue_stage(A, W, m0, n0, (it + 2) * 16, sm + nbuf * STAGE_FLOATS, tid);
        }

        const float* as = sm + buf * STAGE_FLOATS;
        const float* bs = as + A_STAGE;

#pragma unroll
        for (int k8 = 0; k8 < 16; k8 += 8) {
            unsigned ah[2][4], al[2][4];
#pragma unroll
            for (int mt = 0; mt < 2; mt++) {
                int mb = wm * 32 + mt * 16;
                float v0 = as[(mb + g) * AS_W + k8 + tg];
                float v1 = as[(mb + g + 8) * AS_W + k8 + tg];
                float v2 = as[(mb + g) * AS_W + k8 + tg + 4];
                float v3 = as[(mb + g + 8) * AS_W + k8 + tg + 4];
                ah[mt][0] = f2tf(v0); al[mt][0] = f2tf(v0 - __uint_as_float(ah[mt][0]));
                ah[mt][1] = f2tf(v1); al[mt][1] = f2tf(v1 - __uint_as_float(ah[mt][1]));
                ah[mt][2] = f2tf(v2); al[mt][2] = f2tf(v2 - __uint_as_float(ah[mt][2]));
                ah[mt][3] = f2tf(v3); al[mt][3] = f2tf(v3 - __uint_as_float(ah[mt][3]));
            }
#pragma unroll
            for (int nt = 0; nt < 8; nt++) {
                int nb = wn * 64 + nt * 8;
                float b0 = bs[(k8 + tg) * BS_W + nb + g];
                float b1 = bs[(k8 + tg + 4) * BS_W + nb + g];
                unsigned bh[2], bl[2];
                bh[0] = f2tf(b0); bl[0] = f2tf(b0 - __uint_as_float(bh[0]));
                bh[1] = f2tf(b1); bl[1] = f2tf(b1 - __uint_as_float(bh[1]));
#pragma unroll
                for (int mt = 0; mt < 2; mt++) {
                    mma_tf32(c[mt][nt], ah[mt], bh);
                    mma_tf32(c[mt][nt], ah[mt], bl);
                    mma_tf32(c[mt][nt], al[mt], bh);
                }
            }
        }
        buf++; if (buf >= NSTAGE) buf = 0;
    }

#pragma unroll
    for (int mt = 0; mt < 2; mt++)
#pragma unroll
        for (int nt = 0; nt < 8; nt++)
#pragma unroll
            for (int ci = 0; ci < 4; ci++) {
                int row = m0 + wm * 32 + mt * 16 + g + (ci >> 1) * 8;
                int col = n0 + wn * 64 + nt * 8 + tg * 2 + (ci & 1);
                float v = fmaxf(c[mt][nt][ci] + bias[col], 0.f);
                if (SCATTER) {
                    int b = row >> 10, s = row & 1023;
                    int h = col >> 6, d = col & 63;
                    out[(((size_t)(b * NH + h)) * SQ + s) * DKH + d] = v;
                } else {
                    out[(size_t)row * 1024 + col] = v;
                }
            }
}

// z = 0/1/2: q/k/v projections. z = 3: bernoulli slice (overlaps on ALU pipes).
__global__ void __launch_bounds__(256) qkv_gemm_kernel(
    const float* __restrict__ x,
    const float* __restrict__ Wq, const float* __restrict__ bq, float* __restrict__ oq,
    const float* __restrict__ Wk, const float* __restrict__ bk, float* __restrict__ ok,
    const float* __restrict__ Wv, const float* __restrict__ bv, float* __restrict__ ov)
{
    if (blockIdx.z == 3) {
        bern_chunk(blockIdx.y * 8 + blockIdx.x, threadIdx.x);
        return;
    }
    const float* W; const float* bias; float* out;
    if (blockIdx.z == 0)      { W = Wq; bias = bq; out = oq; }
    else if (blockIdx.z == 1) { W = Wk; bias = bk; out = ok; }
    else                      { W = Wv; bias = bv; out = ov; }
    gemm_body<1>(x, W, bias, out);
}

__global__ void __launch_bounds__(256) out_gemm_kernel(
    const float* __restrict__ A, const float* __restrict__ W,
    const float* __restrict__ bias, float* __restrict__ out)
{
    gemm_body<0>(A, W, bias, out);
}

// ---------------- V suffix sums ---------------------------------------------
__global__ void __launch_bounds__(1024) vsuf_kernel() {
    int bh = blockIdx.x;
    __shared__ float part[32][64];
    int d = threadIdx.x & 63;
    int jj = threadIdx.x >> 6;
#pragma unroll
    for (int p = 0; p < 2; p++) {
        int j = p * 16 + jj;
        const float* vp = g_v + ((size_t)bh * 1024 + j * 32) * 64 + d;
        float sum = 0.f;
#pragma unroll
        for (int s = 0; s < 32; s++) sum += vp[s * 64];
        part[j][d] = sum;
    }
    __syncthreads();
    if (threadIdx.x < 64) {
        float run = 0.f;
        for (int j = 31; j >= 0; j--) {
            run += part[j][threadIdx.x];
            g_vsuf[((size_t)bh * 32 + j) * 64 + threadIdx.x] = run;
        }
    }
}

// ---------------- MMA flash attention ----------------------------------------
#define KS_W 76
#define VS_W 72
#define PS_W 33
#define PT_W 36
#define SMEM_ATTN_FLOATS (2*32*KS_W + 2*32*VS_W + 128*PS_W + 8*16*PT_W)
#define SMEM_ATTN_BYTES (SMEM_ATTN_FLOATS * 4)

__global__ void __launch_bounds__(256) attn_kernel(
    const float* __restrict__ pos, const int* __restrict__ mask)
{
    extern __shared__ float sm[];
    float* Ks_hi = sm;
    float* Ks_lo = Ks_hi + 32 * KS_W;
    float* Vs_hi = Ks_lo + 32 * KS_W;
    float* Vs_lo = Vs_hi + 32 * VS_W;
    float* ps    = Vs_lo + 32 * VS_W;
    float* PtAll = ps + 128 * PS_W;

    int qb = blockIdx.x, h = blockIdx.y, b = blockIdx.z;
    int tid = threadIdx.x;
    int lane = tid & 31, warp = tid >> 5;
    int g = lane >> 2, tg = lane & 3;
    float* Pt = PtAll + warp * 16 * PT_W;

    int qr0 = qb * 128 + warp * 16;
    int qrow_g = qr0 + g;
    int qrow_h = qr0 + g + 8;
    size_t bh = (size_t)(b * NH + h);

    unsigned qa_hi[8][4], qa_lo[8][4];
    {
        const float* qbase = g_q + (bh * SQ + qr0) * DKH;
#pragma unroll
        for (int ks = 0; ks < 8; ks++) {
            float v0 = qbase[g * 64 + ks * 8 + tg];
            float v1 = qbase[(g + 8) * 64 + ks * 8 + tg];
            float v2 = qbase[g * 64 + ks * 8 + tg + 4];
            float v3 = qbase[(g + 8) * 64 + ks * 8 + tg + 4];
            qa_hi[ks][0] = f2tf(v0); qa_lo[ks][0] = f2tf(v0 - __uint_as_float(qa_hi[ks][0]));
            qa_hi[ks][1] = f2tf(v1); qa_lo[ks][1] = f2tf(v1 - __uint_as_float(qa_hi[ks][1]));
            qa_hi[ks][2] = f2tf(v2); qa_lo[ks][2] = f2tf(v2 - __uint_as_float(qa_hi[ks][2]));
            qa_hi[ks][3] = f2tf(v3); qa_lo[ks][3] = f2tf(v3 - __uint_as_float(qa_hi[ks][3]));
        }
    }

    float o[8][4];
#pragma unroll
    for (int nt = 0; nt < 8; nt++)
#pragma unroll
        for (int i = 0; i < 4; i++) o[nt][i] = 0.f;
    float m_g = -INFINITY, m_h = -INFINITY, l_g = 0.f, l_h = 0.f;

    int kb_end = (qb + 1) * 128;
    int ld_d = tid & 63;
    int ld_kg = tid >> 6;

    for (int kb = 0; kb < kb_end; kb += 32) {
        __syncthreads();
        {
            const float* kgp = g_k + (bh * SQ + kb) * DKH;
            const float* vgp = g_v + (bh * SQ + kb) * DKH;
#pragma unroll
            for (int ki = 0; ki < 8; ki++) {
                int key = ld_kg * 8 + ki;
                float kv = kgp[key * 64 + ld_d];
                float vv = vgp[key * 64 + ld_d];
                unsigned khi = f2tf(kv);
                unsigned vhi = f2tf(vv);
                Ks_hi[key * KS_W + ld_d] = __uint_as_float(khi);
                Ks_lo[key * KS_W + ld_d] = __uint_as_float(f2tf(kv - __uint_as_float(khi)));
                Vs_hi[key * VS_W + ld_d] = __uint_as_float(vhi);
                Vs_lo[key * VS_W + ld_d] = __uint_as_float(f2tf(vv - __uint_as_float(vhi)));
            }
#pragma unroll
            for (int i = 0; i < 16; i++) {
                int idx = tid + i * 256;
                int r = idx >> 5, cc = idx & 31;
                ps[r * PS_W + cc] = pos[((size_t)b * SQ + qb * 128 + r) * SQ + kb + cc];
            }
        }
        __syncthreads();

        if (kb <= qr0) {
            float sc[4][4];
#pragma unroll
            for (int nt = 0; nt < 4; nt++)
#pragma unroll
                for (int i = 0; i < 4; i++) sc[nt][i] = 0.f;
#pragma unroll
            for (int ks = 0; ks < 8; ks++) {
#pragma unroll
                for (int nt = 0; nt < 4; nt++) {
                    unsigned bhh[2], bll[2];
                    bhh[0] = __float_as_uint(Ks_hi[(nt * 8 + g) * KS_W + ks * 8 + tg]);
                    bhh[1] = __float_as_uint(Ks_hi[(nt * 8 + g) * KS_W + ks * 8 + tg + 4]);
                    bll[0] = __float_as_uint(Ks_lo[(nt * 8 + g) * KS_W + ks * 8 + tg]);
                    bll[1] = __float_as_uint(Ks_lo[(nt * 8 + g) * KS_W + ks * 8 + tg + 4]);
                    mma_tf32(sc[nt], qa_hi[ks], bhh);
                    mma_tf32(sc[nt], qa_hi[ks], bll);
                    mma_tf32(sc[nt], qa_lo[ks], bhh);
                }
            }

            unsigned bw_g = g_bern[(bh * SQ + qrow_g) * 32u + (kb >> 5)];
            unsigned bw_h = g_bern[(bh * SQ + qrow_h) * 32u + (kb >> 5)];
            unsigned mw = __ballot_sync(0xffffffffu, mask[b * SQ + kb + lane] != 0);

            float vals[4][4];
#pragma unroll
            for (int nt = 0; nt < 4; nt++) {
                int c0 = nt * 8 + tg * 2, c1 = c0 + 1;
                float v00 = sc[nt][0] * 0.125f + ps[(warp * 16 + g) * PS_W + c0];
                float v01 = sc[nt][1] * 0.125f + ps[(warp * 16 + g) * PS_W + c1];
                float v10 = sc[nt][2] * 0.125f + ps[(warp * 16 + g + 8) * PS_W + c0];
                float v11 = sc[nt][3] * 0.125f + ps[(warp * 16 + g + 8) * PS_W + c1];
                if ((bw_g >> c0) & 1u) v00 += -1e9f;
                if ((bw_g >> c1) & 1u) v01 += -1e9f;
                if ((bw_h >> c0) & 1u) v10 += -1e9f;
                if ((bw_h >> c1) & 1u) v11 += -1e9f;
                int kg0 = kb + c0, kg1 = kb + c1;
                if (((mw >> c0) & 1u) | (unsigned)(kg0 > qrow_g)) v00 = -1e9f;
                if (((mw >> c1) & 1u) | (unsigned)(kg1 > qrow_g)) v01 = -1e9f;
                if (((mw >> c0) & 1u) | (unsigned)(kg0 > qrow_h)) v10 = -1e9f;
                if (((mw >> c1) & 1u) | (unsigned)(kg1 > qrow_h)) v11 = -1e9f;
                vals[nt][0] = v00; vals[nt][1] = v01;
                vals[nt][2] = v10; vals[nt][3] = v11;
            }

            float rmax_g = vals[0][0], rmax_h = vals[0][2];
#pragma unroll
            for (int nt = 0; nt < 4; nt++) {
                rmax_g = fmaxf(rmax_g, fmaxf(vals[nt][0], vals[nt][1]));
                rmax_h = fmaxf(rmax_h, fmaxf(vals[nt][2], vals[nt][3]));
            }
            rmax_g = fmaxf(rmax_g, __shfl_xor_sync(0xffffffffu, rmax_g, 1));
            rmax_g = fmaxf(rmax_g, __shfl_xor_sync(0xffffffffu, rmax_g, 2));
            rmax_h = fmaxf(rmax_h, __shfl_xor_sync(0xffffffffu, rmax_h, 1));
            rmax_h = fmaxf(rmax_h, __shfl_xor_sync(0xffffffffu, rmax_h, 2));

            float mn_g = fmaxf(m_g, rmax_g);
            float mn_h = fmaxf(m_h, rmax_h);
            float corr_g = __expf(m_g - mn_g);
            float corr_h = __expf(m_h - mn_h);
            m_g = mn_g; m_h = mn_h;
            l_g *= corr_g; l_h *= corr_h;
#pragma unroll
            for (int nt = 0; nt < 8; nt++) {
                o[nt][0] *= corr_g; o[nt][1] *= corr_g;
                o[nt][2] *= corr_h; o[nt][3] *= corr_h;
            }

            float psum_g = 0.f, psum_h = 0.f;
#pragma unroll
            for (int nt = 0; nt < 4; nt++) {
                int c0 = nt * 8 + tg * 2;
                float p00 = __expf(vals[nt][0] - m_g);
                float p01 = __expf(vals[nt][1] - m_g);
                float p10 = __expf(vals[nt][2] - m_h);
                float p11 = __expf(vals[nt][3] - m_h);
                psum_g += p00 + p01;
                psum_h += p10 + p11;
                *(float2*)&Pt[g * PT_W + c0] = make_float2(p00, p01);
                *(float2*)&Pt[(g + 8) * PT_W + c0] = make_float2(p10, p11);
            }
            psum_g += __shfl_xor_sync(0xffffffffu, psum_g, 1);
            psum_g += __shfl_xor_sync(0xffffffffu, psum_g, 2);
            psum_h += __shfl_xor_sync(0xffffffffu, psum_h, 1);
            psum_h += __shfl_xor_sync(0xffffffffu, psum_h, 2);
            l_g += psum_g; l_h += psum_h;

            __syncwarp();

#pragma unroll
            for (int ks = 0; ks < 4; ks++) {
                float p0 = Pt[g * PT_W + ks * 8 + tg];
                float p1 = Pt[(g + 8) * PT_W + ks * 8 + tg];
                float p2 = Pt[g * PT_W + ks * 8 + tg + 4];
                float p3 = Pt[(g + 8) * PT_W + ks * 8 + tg + 4];
                unsigned pa_hi[4], pa_lo[4];
                pa_hi[0] = f2tf(p0); pa_lo[0] = f2tf(p0 - __uint_as_float(pa_hi[0]));
                pa_hi[1] = f2tf(p1); pa_lo[1] = f2tf(p1 - __uint_as_float(pa_hi[1]));
                pa_hi[2] = f2tf(p2); pa_lo[2] = f2tf(p2 - __uint_as_float(pa_hi[2]));
                pa_hi[3] = f2tf(p3); pa_lo[3] = f2tf(p3 - __uint_as_float(pa_hi[3]));
#pragma unroll
                for (int nt = 0; nt < 8; nt++) {
                    unsigned bhh[2], bll[2];
                    bhh[0] = __float_as_uint(Vs_hi[(ks * 8 + tg) * VS_W + nt * 8 + g]);
                    bhh[1] = __float_as_uint(Vs_hi[(ks * 8 + tg + 4) * VS_W + nt * 8 + g]);
                    bll[0] = __float_as_uint(Vs_lo[(ks * 8 + tg) * VS_W + nt * 8 + g]);
                    bll[1] = __float_as_uint(Vs_lo[(ks * 8 + tg + 4) * VS_W + nt * 8 + g]);
                    mma_tf32(o[nt], pa_hi, bhh);
                    mma_tf32(o[nt], pa_hi, bll);
                    mma_tf32(o[nt], pa_lo, bhh);
                }
            }
            __syncwarp();
        }
    }

    int jt = (qrow_g >> 5) + 1;
    if (jt < 32) {
        float pt_g = __expf(-1e9f - m_g);
        float pt_h = __expf(-1e9f - m_h);
        l_g += pt_g * (float)(1024 - jt * 32);
        l_h += pt_h * (float)(1024 - jt * 32);
        const float* sp = g_vsuf + (bh * 32 + jt) * 64;
#pragma unroll
        for (int nt = 0; nt < 8; nt++) {
            int c0 = nt * 8 + tg * 2;
            float s0 = sp[c0], s1 = sp[c0 + 1];
            o[nt][0] = fmaf(pt_g, s0, o[nt][0]);
            o[nt][1] = fmaf(pt_g, s1, o[nt][1]);
            o[nt][2] = fmaf(pt_h, s0, o[nt][2]);
            o[nt][3] = fmaf(pt_h, s1, o[nt][3]);
        }
    }

    float ig = 1.0f / l_g, ih = 1.0f / l_h;
    float* og = g_ao + (((size_t)b * SQ + qrow_g) * NH + h) * DKH;
    float* oh = g_ao + (((size_t)b * SQ + qrow_h) * NH + h) * DKH;
#pragma unroll
    for (int nt = 0; nt < 8; nt++) {
        int c0 = nt * 8 + tg * 2;
        *(float2*)(og + c0) = make_float2(o[nt][0] * ig, o[nt][1] * ig);
        *(float2*)(oh + c0) = make_float2(o[nt][2] * ih, o[nt][3] * ih);
    }
}

// ---------------- launch ----------------------------------------------------
extern "C" void kernel_launch(void* const* d_in, const int* in_sizes, int n_in,
                              void* d_out, int out_size) {
    (void)in_sizes; (void)n_in; (void)out_size;
    const float* x    = (const float*)d_in[0];
    const int*   mask = (const int*)d_in[1];
    const float* pos  = (const float*)d_in[2];
    const float* Wq = (const float*)d_in[4];
    const float* bq = (const float*)d_in[5];
    const float* Wk = (const float*)d_in[6];
    const float* bk = (const float*)d_in[7];
    const float* Wv = (const float*)d_in[8];
    const float* bv = (const float*)d_in[9];
    const float* Wo = (const float*)d_in[10];
    const float* bo = (const float*)d_in[11];
    float* out = (float*)d_out;

    float *pq, *pk, *pv, *pao;
    cudaGetSymbolAddress((void**)&pq,  g_q);
    cudaGetSymbolAddress((void**)&pk,  g_k);
    cudaGetSymbolAddress((void**)&pv,  g_v);
    cudaGetSymbolAddress((void**)&pao, g_ao);

    static int smem_set = 0;
    if (!smem_set) {
        cudaFuncSetAttribute(qkv_gemm_kernel,
            cudaFuncAttributeMaxDynamicSharedMemorySize, SMEM_GEMM_BYTES);
        cudaFuncSetAttribute(out_gemm_kernel,
            cudaFuncAttributeMaxDynamicSharedMemorySize, SMEM_GEMM_BYTES);
        cudaFuncSetAttribute(attn_kernel,
            cudaFuncAttributeMaxDynamicSharedMemorySize, SMEM_ATTN_BYTES);
        smem_set = 1;
    }

    // z=0..2: Q/K/V projections; z=3: bernoulli bits (overlapped on ALU pipes)
    dim3 gg(8, 32, 4);
    qkv_gemm_kernel<<<gg, 256, SMEM_GEMM_BYTES>>>(
        x, Wq, bq, pq, Wk, bk, pk, Wv, bv, pv);

    vsuf_kernel<<<64, 1024>>>();

    dim3 ga(8, NH, NB);
    attn_kernel<<<ga, 256, SMEM_ATTN_BYTES>>>(pos, mask);

    dim3 go(8, 32, 1);
    out_gemm_kernel<<<go, 256, SMEM_GEMM_BYTES>>>(pao, Wo, bo, out);
}